// round 7
// baseline (speedup 1.0000x reference)
#include <cuda_runtime.h>
#include <cuda_bf16.h>
#include <cstdint>
#include <math.h>

#define Bn  8
#define Cin 1024
#define Sn  2048
#define KD  512
#define OD  1024
#define QKN 1024   // merged q|k output width

typedef __nv_bfloat16 bf16;

// ---------------- scratch: separate hi / lo planes --------------------------
__device__ __align__(128) bf16 g_xT_h[(size_t)Bn * Sn * Cin];
__device__ __align__(128) bf16 g_xT_l[(size_t)Bn * Sn * Cin];
__device__ __align__(128) bf16 g_wqk_h[(size_t)QKN * Cin];
__device__ __align__(128) bf16 g_wqk_l[(size_t)QKN * Cin];
__device__ __align__(128) bf16 g_wv_h[(size_t)OD * Cin];
__device__ __align__(128) bf16 g_wv_l[(size_t)OD * Cin];
__device__ __align__(128) float g_bqk[QKN];
__device__ __align__(128) bf16 g_qk_h[(size_t)Bn * Sn * QKN];  // q cols 0-511, k cols 512-1023
__device__ __align__(128) bf16 g_qk_l[(size_t)Bn * Sn * QKN];
__device__ __align__(128) bf16 g_v_h[(size_t)Bn * OD * Sn];
__device__ __align__(128) bf16 g_v_l[(size_t)Bn * OD * Sn];
__device__ __align__(128) bf16 g_e_h[(size_t)Bn * Sn * Sn];    // unnormalized exp(scores)
__device__ __align__(128) bf16 g_e_l[(size_t)Bn * Sn * Sn];
__device__ __align__(128) float g_psum[(size_t)Bn * 16 * Sn];  // partial row sums per n-tile
__device__ __align__(128) float g_inv[(size_t)Bn * Sn];        // 1/rowsum

// ---------------- helpers ----------------------------------------------------
__device__ __forceinline__ uint32_t smem_u32(const void* p) {
    uint32_t a;
    asm("{ .reg .u64 t; cvta.to.shared.u64 t, %1; cvt.u32.u64 %0, t; }" : "=r"(a) : "l"(p));
    return a;
}

__device__ __forceinline__ void split_hl(float v, bf16& h, bf16& l) {
    h = __float2bfloat16(v);
    l = __float2bfloat16(v - __bfloat162float(h));
}

#define LDSM_X4(r0, r1, r2, r3, addr) \
    asm volatile("ldmatrix.sync.aligned.m8n8.x4.shared.b16 {%0,%1,%2,%3}, [%4];" \
                 : "=r"(r0), "=r"(r1), "=r"(r2), "=r"(r3) : "r"(addr))

__device__ __forceinline__ void mma16816(float* d, const uint32_t* a, const uint32_t* b) {
    asm volatile(
        "mma.sync.aligned.m16n8k16.row.col.f32.bf16.bf16.f32 "
        "{%0,%1,%2,%3}, {%4,%5,%6,%7}, {%8,%9}, {%0,%1,%2,%3};"
        : "+f"(d[0]), "+f"(d[1]), "+f"(d[2]), "+f"(d[3])
        : "r"(a[0]), "r"(a[1]), "r"(a[2]), "r"(a[3]), "r"(b[0]), "r"(b[1]));
}

#define CP_ASYNC16(dst, src) \
    asm volatile("cp.async.cg.shared.global [%0], [%1], 16;" :: "r"(dst), "l"(src) : "memory")
#define CP_COMMIT()  asm volatile("cp.async.commit_group;" ::: "memory")
#define CP_WAIT(n)   asm volatile("cp.async.wait_group %0;" :: "n"(n) : "memory")

// ---------------- smem: 4 stages x (Ah 8K | Al 8K | Bh 8K | Bl 8K) ----------
#define STAGE_BYTES 32768
#define NSTAGE      4
#define SM_TOTAL    (NSTAGE * STAGE_BYTES)
// tile: 128 rows x 32 bf16 (64B rows); 16B-chunk swizzle: c4 ^= (row>>1)&3

__device__ __forceinline__ void cp_tile(uint32_t sdst, const bf16* __restrict__ g,
                                        int ld, int row0, int kc, int tid) {
#pragma unroll
    for (int it = 0; it < 2; it++) {
        int slot = tid + it * 256;
        int row  = slot >> 2;
        int c4   = slot & 3;
        uint32_t off = (uint32_t)row * 64 + (uint32_t)((c4 ^ ((row >> 1) & 3)) << 4);
        CP_ASYNC16(sdst + off, g + (size_t)(row0 + row) * ld + kc * 32 + c4 * 8);
    }
}

// ---------------- bf16x3 mma.sync GEMM with 4-stage cp.async pipeline -------
// D[m,n] = alpha * sum_k A[m,k]*B[n,k]; A,B hi/lo bf16 planes, K-major.
// EPI: 1 = +bias[n], HL-plane out           (qk projection)
//      2 = +bias[m], HL-plane out           (v projection)
//      3 = exp(d), HL-plane out + psum      (scores -> unnormalized softmax)
//      4 = d * aux[b*Sn + n], fp32 out      (PV with deferred normalization)
template<int EPI>
__global__ void __launch_bounds__(256)
gemm_mma(const bf16* __restrict__ Ah, const bf16* __restrict__ Al,
         const bf16* __restrict__ Bh, const bf16* __restrict__ Bl,
         const float* __restrict__ bias, float* __restrict__ aux,
         void* __restrict__ Ch, void* __restrict__ Cl,
         int lda, int ldb, int ldc, int nK,
         size_t sA, size_t sB, size_t sC, float alpha)
{
    extern __shared__ __align__(1024) char smem[];
    const uint32_t sm = smem_u32(smem);
    const int tid  = threadIdx.x;
    const int lane = tid & 31;
    const int wid  = tid >> 5;
    const int m0   = blockIdx.y * 128;
    const int n0   = blockIdx.x * 128;
    const int mW   = (wid >> 2) * 64;
    const int nW   = (wid & 3) * 32;

    Ah += (size_t)blockIdx.z * sA;  Al += (size_t)blockIdx.z * sA;
    Bh += (size_t)blockIdx.z * sB;  Bl += (size_t)blockIdx.z * sB;

    float acc[4][4][4];
#pragma unroll
    for (int i = 0; i < 4; i++)
#pragma unroll
        for (int j = 0; j < 4; j++) {
            acc[i][j][0] = 0.f; acc[i][j][1] = 0.f; acc[i][j][2] = 0.f; acc[i][j][3] = 0.f;
        }

    const uint32_t rl   = lane & 15;
    const uint32_t khA  = lane >> 4;
    const uint32_t swA  = (rl >> 1) & 3;
    const uint32_t aRow = (uint32_t)(mW + rl) * 64;
    const uint32_t rnl  = ((lane >> 4) << 3) | (lane & 7);
    const uint32_t khB  = (lane >> 3) & 1;
    const uint32_t swB  = (rnl >> 1) & 3;
    const uint32_t bRow = (uint32_t)(nW + rnl) * 64;

    // prologue: stages 0, 1, 2
#pragma unroll
    for (int p = 0; p < 3; p++) {
        if (p < nK) {
            const uint32_t st = sm + p * STAGE_BYTES;
            cp_tile(st,         Ah, lda, m0, p, tid);
            cp_tile(st + 8192,  Al, lda, m0, p, tid);
            cp_tile(st + 16384, Bh, ldb, n0, p, tid);
            cp_tile(st + 24576, Bl, ldb, n0, p, tid);
        }
        CP_COMMIT();
    }

    for (int i = 0; i < nK; i++) {
        CP_WAIT(2);
        __syncthreads();

        // issue stage i+3 FIRST (its buffer's readers joined at this barrier)
        const int nx = i + 3;
        if (nx < nK) {
            const uint32_t st = sm + (uint32_t)(nx % NSTAGE) * STAGE_BYTES;
            cp_tile(st,         Ah, lda, m0, nx, tid);
            cp_tile(st + 8192,  Al, lda, m0, nx, tid);
            cp_tile(st + 16384, Bh, ldb, n0, nx, tid);
            cp_tile(st + 24576, Bl, ldb, n0, nx, tid);
        }
        CP_COMMIT();

        const uint32_t stg = sm + (uint32_t)(i % NSTAGE) * STAGE_BYTES;
#pragma unroll
        for (int ks = 0; ks < 2; ks++) {
            const uint32_t aCh = (uint32_t)((ks * 2 + khA) ^ swA) << 4;
            const uint32_t bCh = (uint32_t)((ks * 2 + khB) ^ swB) << 4;
            uint32_t ah[4][4], al[4][4], bh[8], bl[8];
#pragma unroll
            for (int mt = 0; mt < 4; mt++) {
                LDSM_X4(ah[mt][0], ah[mt][1], ah[mt][2], ah[mt][3],
                        stg + aRow + mt * 1024 + aCh);
                LDSM_X4(al[mt][0], al[mt][1], al[mt][2], al[mt][3],
                        stg + 8192 + aRow + mt * 1024 + aCh);
            }
            LDSM_X4(bh[0], bh[1], bh[2], bh[3], stg + 16384 + bRow + bCh);
            LDSM_X4(bh[4], bh[5], bh[6], bh[7], stg + 16384 + bRow + 1024 + bCh);
            LDSM_X4(bl[0], bl[1], bl[2], bl[3], stg + 24576 + bRow + bCh);
            LDSM_X4(bl[4], bl[5], bl[6], bl[7], stg + 24576 + bRow + 1024 + bCh);

#pragma unroll
            for (int mt = 0; mt < 4; mt++)
#pragma unroll
                for (int nt = 0; nt < 4; nt++) {
                    mma16816(acc[mt][nt], ah[mt], &bh[nt * 2]);
                    mma16816(acc[mt][nt], ah[mt], &bl[nt * 2]);
                    mma16816(acc[mt][nt], al[mt], &bh[nt * 2]);
                }
        }
    }
    __syncthreads();   // mainloop done; smem reusable below

    // ---- epilogue ----
    const int g  = lane >> 2;
    const int tg = lane & 3;
    float rsum[4][2];
    if (EPI == 3) {
#pragma unroll
        for (int mt = 0; mt < 4; mt++) { rsum[mt][0] = 0.f; rsum[mt][1] = 0.f; }
    }

#pragma unroll
    for (int mt = 0; mt < 4; mt++) {
        const int m = m0 + mW + mt * 16 + g;
        float bm0 = 0.f, bm8 = 0.f;
        if (EPI == 2) { bm0 = bias[m]; bm8 = bias[m + 8]; }
#pragma unroll
        for (int nt = 0; nt < 4; nt++) {
            const int n = n0 + nW + nt * 8 + tg * 2;
            float d0 = acc[mt][nt][0] * alpha;
            float d1 = acc[mt][nt][1] * alpha;
            float d2 = acc[mt][nt][2] * alpha;
            float d3 = acc[mt][nt][3] * alpha;
            if (EPI == 1) {
                float2 bb = *(const float2*)(bias + n);
                d0 += bb.x; d1 += bb.y; d2 += bb.x; d3 += bb.y;
            } else if (EPI == 2) {
                d0 += bm0; d1 += bm0; d2 += bm8; d3 += bm8;
            } else if (EPI == 3) {
                d0 = __expf(d0); d1 = __expf(d1); d2 = __expf(d2); d3 = __expf(d3);
                rsum[mt][0] += d0 + d1;
                rsum[mt][1] += d2 + d3;
            } else if (EPI == 4) {
                float2 iv = *(const float2*)(aux + (size_t)blockIdx.z * Sn + n);
                d0 *= iv.x; d1 *= iv.y; d2 *= iv.x; d3 *= iv.y;
            }
            if (EPI == 4) {
                float* C = (float*)Ch + (size_t)blockIdx.z * sC;
                float2 o0 = { d0, d1 };
                float2 o1 = { d2, d3 };
                *(float2*)(C + (size_t)m * ldc + n)       = o0;
                *(float2*)(C + (size_t)(m + 8) * ldc + n) = o1;
            } else {
                bf16 h0, l0, h1, l1, h2, l2, h3, l3;
                split_hl(d0, h0, l0); split_hl(d1, h1, l1);
                split_hl(d2, h2, l2); split_hl(d3, h3, l3);
                bf16* CH = (bf16*)Ch + (size_t)blockIdx.z * sC;
                bf16* CL = (bf16*)Cl + (size_t)blockIdx.z * sC;
                *(__nv_bfloat162*)(CH + (size_t)m * ldc + n)       = __nv_bfloat162(h0, h1);
                *(__nv_bfloat162*)(CH + (size_t)(m + 8) * ldc + n) = __nv_bfloat162(h2, h3);
                *(__nv_bfloat162*)(CL + (size_t)m * ldc + n)       = __nv_bfloat162(l0, l1);
                *(__nv_bfloat162*)(CL + (size_t)(m + 8) * ldc + n) = __nv_bfloat162(l2, l3);
            }
        }
    }

    if (EPI == 3) {
        // reduce partial row sums: across tg lanes, then across the 4 n-warps
#pragma unroll
        for (int mt = 0; mt < 4; mt++) {
#pragma unroll
            for (int h = 0; h < 2; h++) {
                float s = rsum[mt][h];
                s += __shfl_xor_sync(0xffffffffu, s, 1);
                s += __shfl_xor_sync(0xffffffffu, s, 2);
                rsum[mt][h] = s;
            }
        }
        float* ss = (float*)smem;               // [4 n-warps][128 rows]
        const int nWj = wid & 3;
        if (tg == 0) {
#pragma unroll
            for (int mt = 0; mt < 4; mt++) {
                ss[nWj * 128 + mW + mt * 16 + g]     = rsum[mt][0];
                ss[nWj * 128 + mW + mt * 16 + 8 + g] = rsum[mt][1];
            }
        }
        __syncthreads();
        if (tid < 128) {
            float t = ss[tid] + ss[128 + tid] + ss[256 + tid] + ss[384 + tid];
            aux[((size_t)blockIdx.z * 16 + blockIdx.x) * Sn + m0 + tid] = t;
        }
    }
}

// ---------------- converters --------------------------------------------------
__global__ void __launch_bounds__(256)
xpose_pack(const float* __restrict__ x, bf16* __restrict__ xh, bf16* __restrict__ xl)
{
    __shared__ float t[32][33];
    const int tx = threadIdx.x, ty = threadIdx.y;
    const int s0 = blockIdx.x * 32, c0 = blockIdx.y * 32;
    const size_t bi = (size_t)blockIdx.z * Cin * Sn;
    const size_t bo = (size_t)blockIdx.z * Sn * Cin;
#pragma unroll
    for (int j = ty; j < 32; j += 8)
        t[j][tx] = x[bi + (size_t)(c0 + j) * Sn + s0 + tx];
    __syncthreads();
#pragma unroll
    for (int j = ty; j < 32; j += 8) {
        bf16 h, l;
        split_hl(t[tx][j], h, l);
        xh[bo + (size_t)(s0 + j) * Cin + c0 + tx] = h;
        xl[bo + (size_t)(s0 + j) * Cin + c0 + tx] = l;
    }
}

__global__ void __launch_bounds__(256)
pack_f32(const float* __restrict__ in, bf16* __restrict__ oh, bf16* __restrict__ ol, int n4)
{
    int i = blockIdx.x * 256 + threadIdx.x;
    if (i < n4) {
        float4 v = ((const float4*)in)[i];
        bf16 h0, l0, h1, l1, h2, l2, h3, l3;
        split_hl(v.x, h0, l0); split_hl(v.y, h1, l1);
        split_hl(v.z, h2, l2); split_hl(v.w, h3, l3);
        uint2 ho, lo;
        ho.x = (uint32_t)__bfloat16_as_ushort(h0) | ((uint32_t)__bfloat16_as_ushort(h1) << 16);
        ho.y = (uint32_t)__bfloat16_as_ushort(h2) | ((uint32_t)__bfloat16_as_ushort(h3) << 16);
        lo.x = (uint32_t)__bfloat16_as_ushort(l0) | ((uint32_t)__bfloat16_as_ushort(l1) << 16);
        lo.y = (uint32_t)__bfloat16_as_ushort(l2) | ((uint32_t)__bfloat16_as_ushort(l3) << 16);
        ((uint2*)oh)[i] = ho;
        ((uint2*)ol)[i] = lo;
    }
}

// rowsum over the 16 n-tiles -> reciprocal
__global__ void __launch_bounds__(256)
reduce_inv(const float* __restrict__ psum, float* __restrict__ inv)
{
    int i = blockIdx.x * 256 + threadIdx.x;     // over Bn*Sn
    int b = i >> 11, s = i & 2047;
    const float* p = psum + (size_t)b * 16 * Sn + s;
    float t = 0.f;
#pragma unroll
    for (int j = 0; j < 16; j++) t += p[(size_t)j * Sn];
    inv[i] = 1.0f / t;
}

// -----------------------------------------------------------------------------
extern "C" void kernel_launch(void* const* d_in, const int* in_sizes, int n_in,
                              void* d_out, int out_size)
{
    (void)in_sizes; (void)n_in; (void)out_size;
    const float* x  = (const float*)d_in[0];
    const float* wq = (const float*)d_in[1];
    const float* bq = (const float*)d_in[2];
    const float* wk = (const float*)d_in[3];
    const float* bk = (const float*)d_in[4];
    const float* wv = (const float*)d_in[5];
    const float* bv = (const float*)d_in[6];
    float* out = (float*)d_out;

    bf16 *xh, *xl, *wqkh, *wqkl, *wvh, *wvl, *qkh, *qkl, *vh, *vl, *eh, *el;
    float *bqk, *psum, *inv;
    cudaGetSymbolAddress((void**)&xh,   g_xT_h);  cudaGetSymbolAddress((void**)&xl,   g_xT_l);
    cudaGetSymbolAddress((void**)&wqkh, g_wqk_h); cudaGetSymbolAddress((void**)&wqkl, g_wqk_l);
    cudaGetSymbolAddress((void**)&wvh,  g_wv_h);  cudaGetSymbolAddress((void**)&wvl,  g_wv_l);
    cudaGetSymbolAddress((void**)&bqk,  g_bqk);
    cudaGetSymbolAddress((void**)&qkh,  g_qk_h);  cudaGetSymbolAddress((void**)&qkl,  g_qk_l);
    cudaGetSymbolAddress((void**)&vh,   g_v_h);   cudaGetSymbolAddress((void**)&vl,   g_v_l);
    cudaGetSymbolAddress((void**)&eh,   g_e_h);   cudaGetSymbolAddress((void**)&el,   g_e_l);
    cudaGetSymbolAddress((void**)&psum, g_psum);  cudaGetSymbolAddress((void**)&inv,  g_inv);

    cudaFuncSetAttribute(gemm_mma<1>, cudaFuncAttributeMaxDynamicSharedMemorySize, SM_TOTAL);
    cudaFuncSetAttribute(gemm_mma<2>, cudaFuncAttributeMaxDynamicSharedMemorySize, SM_TOTAL);
    cudaFuncSetAttribute(gemm_mma<3>, cudaFuncAttributeMaxDynamicSharedMemorySize, SM_TOTAL);
    cudaFuncSetAttribute(gemm_mma<4>, cudaFuncAttributeMaxDynamicSharedMemorySize, SM_TOTAL);

    // ---- conversions ----
    xpose_pack<<<dim3(Sn / 32, Cin / 32, Bn), dim3(32, 8)>>>(x, xh, xl);
    pack_f32<<<(KD * Cin / 4 + 255) / 256, 256>>>(wq, wqkh, wqkl, KD * Cin / 4);
    pack_f32<<<(KD * Cin / 4 + 255) / 256, 256>>>(wk, wqkh + (size_t)KD * Cin,
                                                  wqkl + (size_t)KD * Cin, KD * Cin / 4);
    pack_f32<<<(OD * Cin / 4 + 255) / 256, 256>>>(wv, wvh, wvl, OD * Cin / 4);
    cudaMemcpyAsync(bqk,      bq, KD * sizeof(float), cudaMemcpyDeviceToDevice, 0);
    cudaMemcpyAsync(bqk + KD, bk, KD * sizeof(float), cudaMemcpyDeviceToDevice, 0);

    const size_t sxT = (size_t)Sn * Cin;
    const size_t sqk = (size_t)Sn * QKN;
    const size_t sv  = (size_t)OD * Sn;
    const size_t ssc = (size_t)Sn * Sn;

    // qk = xT @ [Wq|Wk]^T + [bq|bk] -> (B,S,1024)   [m=s, n=qk-ch, k=c]
    gemm_mma<1><<<dim3(QKN / 128, Sn / 128, Bn), 256, SM_TOTAL>>>(
        xh, xl, wqkh, wqkl, bqk, nullptr, qkh, qkl,
        Cin, Cin, QKN, Cin / 32, sxT, 0, sqk, 1.0f);

    // v = Wv @ x + bv -> (B,OD,S)   [m=o, n=s, k=c]
    gemm_mma<2><<<dim3(Sn / 128, OD / 128, Bn), 256, SM_TOTAL>>>(
        wvh, wvl, xh, xl, bv, nullptr, vh, vl,
        Cin, Cin, Sn, Cin / 32, 0, sxT, sv, 1.0f);

    // E = exp(q @ k^T / sqrt(KD)) -> planes + partial row sums   [m=s, n=t, k=kd]
    gemm_mma<3><<<dim3(Sn / 128, Sn / 128, Bn), 256, SM_TOTAL>>>(
        qkh, qkl, qkh + KD, qkl + KD, nullptr, psum, eh, el,
        QKN, QKN, Sn, KD / 32, sqk, sqk, ssc, 0.04419417382415922f);

    // inv rowsums
    reduce_inv<<<Bn * Sn / 256, 256>>>(psum, inv);

    // out = (v @ E^T) * inv[s] -> (B,OD,S) fp32 into d_out   [m=o, n=s, k=t]
    gemm_mma<4><<<dim3(Sn / 128, OD / 128, Bn), 256, SM_TOTAL>>>(
        vh, vl, eh, el, nullptr, inv, out, nullptr,
        Sn, Sn, Sn, Sn / 32, sv, ssc, sv, 1.0f);
}

// round 8
// speedup vs baseline: 1.0392x; 1.0392x over previous
#include <cuda_runtime.h>
#include <cuda_bf16.h>
#include <cstdint>
#include <math.h>

#define Bn  8
#define Cin 1024
#define Sn  2048
#define KD  512
#define OD  1024
#define QKN 1024   // merged q|k output width

typedef __nv_bfloat16 bf16;

// ---------------- scratch: separate hi / lo planes --------------------------
__device__ __align__(128) bf16 g_xT_h[(size_t)Bn * Sn * Cin];
__device__ __align__(128) bf16 g_xT_l[(size_t)Bn * Sn * Cin];
__device__ __align__(128) bf16 g_wqk_h[(size_t)QKN * Cin];
__device__ __align__(128) bf16 g_wqk_l[(size_t)QKN * Cin];
__device__ __align__(128) bf16 g_wv_h[(size_t)OD * Cin];
__device__ __align__(128) bf16 g_wv_l[(size_t)OD * Cin];
__device__ __align__(128) float g_bqk[QKN];
__device__ __align__(128) bf16 g_qk_h[(size_t)Bn * Sn * QKN];  // q cols 0-511, k cols 512-1023
__device__ __align__(128) bf16 g_qk_l[(size_t)Bn * Sn * QKN];
__device__ __align__(128) bf16 g_v_h[(size_t)Bn * OD * Sn];
__device__ __align__(128) bf16 g_v_l[(size_t)Bn * OD * Sn];
__device__ __align__(128) bf16 g_e_h[(size_t)Bn * Sn * Sn];    // unnormalized exp(scores)
__device__ __align__(128) bf16 g_e_l[(size_t)Bn * Sn * Sn];
__device__ __align__(128) float g_psum[(size_t)Bn * 8 * Sn];   // partial row sums per n-tile
__device__ __align__(128) float g_inv[(size_t)Bn * Sn];        // 1/rowsum

// ---------------- helpers ----------------------------------------------------
__device__ __forceinline__ uint32_t smem_u32(const void* p) {
    uint32_t a;
    asm("{ .reg .u64 t; cvta.to.shared.u64 t, %1; cvt.u32.u64 %0, t; }" : "=r"(a) : "l"(p));
    return a;
}

__device__ __forceinline__ void split_hl(float v, bf16& h, bf16& l) {
    h = __float2bfloat16(v);
    l = __float2bfloat16(v - __bfloat162float(h));
}

#define LDSM_X4(r0, r1, r2, r3, addr) \
    asm volatile("ldmatrix.sync.aligned.m8n8.x4.shared.b16 {%0,%1,%2,%3}, [%4];" \
                 : "=r"(r0), "=r"(r1), "=r"(r2), "=r"(r3) : "r"(addr))

__device__ __forceinline__ void mma16816(float* d, const uint32_t* a, const uint32_t* b) {
    asm volatile(
        "mma.sync.aligned.m16n8k16.row.col.f32.bf16.bf16.f32 "
        "{%0,%1,%2,%3}, {%4,%5,%6,%7}, {%8,%9}, {%0,%1,%2,%3};"
        : "+f"(d[0]), "+f"(d[1]), "+f"(d[2]), "+f"(d[3])
        : "r"(a[0]), "r"(a[1]), "r"(a[2]), "r"(a[3]), "r"(b[0]), "r"(b[1]));
}

#define CP_ASYNC16(dst, src) \
    asm volatile("cp.async.cg.shared.global [%0], [%1], 16;" :: "r"(dst), "l"(src) : "memory")
#define CP_COMMIT()  asm volatile("cp.async.commit_group;" ::: "memory")
#define CP_WAIT(n)   asm volatile("cp.async.wait_group %0;" :: "n"(n) : "memory")

// ---------------- smem: 3 stages x (Ah 8K | Al 8K | Bh 16K | Bl 16K) --------
// CTA tile 128m x 256n, BK=32. Rows are 64B; 16B-chunk swizzle c4 ^= (row>>1)&3
#define A_PLANE   8192
#define B_PLANE   16384
#define BH_OFF    (2 * A_PLANE)
#define BL_OFF    (2 * A_PLANE + B_PLANE)
#define STAGE_BYTES 49152
#define NSTAGE      3
#define SM_TOTAL    (NSTAGE * STAGE_BYTES)

template<int ROWS>
__device__ __forceinline__ void cp_tile(uint32_t sdst, const bf16* __restrict__ g,
                                        int ld, int row0, int kc, int tid) {
#pragma unroll
    for (int it = 0; it < ROWS / 64; it++) {
        int slot = tid + it * 256;
        int row  = slot >> 2;
        int c4   = slot & 3;
        uint32_t off = (uint32_t)row * 64 + (uint32_t)((c4 ^ ((row >> 1) & 3)) << 4);
        CP_ASYNC16(sdst + off, g + (size_t)(row0 + row) * ld + kc * 32 + c4 * 8);
    }
}

// ---------------- bf16x3 mma.sync GEMM, 128x256 CTA tile --------------------
// D[m,n] = alpha * sum_k A[m,k]*B[n,k]; A,B hi/lo bf16 planes, K-major.
// EPI: 1 = +bias[n], HL-plane out           (qk projection)
//      2 = +bias[m], HL-plane out           (v projection)
//      3 = exp(d), HL-plane out + psum      (scores -> unnormalized softmax)
//      4 = d * aux[b*Sn + n], fp32 out      (PV with deferred normalization)
template<int EPI>
__global__ void __launch_bounds__(256, 1)
gemm_mma(const bf16* __restrict__ Ah, const bf16* __restrict__ Al,
         const bf16* __restrict__ Bh, const bf16* __restrict__ Bl,
         const float* __restrict__ bias, float* __restrict__ aux,
         void* __restrict__ Ch, void* __restrict__ Cl,
         int lda, int ldb, int ldc, int nK,
         size_t sA, size_t sB, size_t sC, float alpha)
{
    extern __shared__ __align__(1024) char smem[];
    const uint32_t sm = smem_u32(smem);
    const int tid  = threadIdx.x;
    const int lane = tid & 31;
    const int wid  = tid >> 5;
    const int m0   = blockIdx.y * 128;
    const int n0   = blockIdx.x * 256;
    const int mW   = (wid >> 2) * 64;      // 2 m-warps
    const int nW   = (wid & 3) * 64;       // 4 n-warps, 64-wide each

    Ah += (size_t)blockIdx.z * sA;  Al += (size_t)blockIdx.z * sA;
    Bh += (size_t)blockIdx.z * sB;  Bl += (size_t)blockIdx.z * sB;

    float acc[4][8][4];
#pragma unroll
    for (int i = 0; i < 4; i++)
#pragma unroll
        for (int j = 0; j < 8; j++) {
            acc[i][j][0] = 0.f; acc[i][j][1] = 0.f; acc[i][j][2] = 0.f; acc[i][j][3] = 0.f;
        }

    // fragment addressing (swizzle folded into 16B-chunk index)
    const uint32_t rl   = lane & 15;
    const uint32_t khA  = lane >> 4;
    const uint32_t swA  = (rl >> 1) & 3;
    const uint32_t aRow = (uint32_t)(mW + rl) * 64;
    const uint32_t rnl  = ((lane >> 4) << 3) | (lane & 7);
    const uint32_t khB  = (lane >> 3) & 1;
    const uint32_t swB  = (rnl >> 1) & 3;
    const uint32_t bRow = (uint32_t)(nW + rnl) * 64;

    // prologue: stages 0, 1
#pragma unroll
    for (int p = 0; p < 2; p++) {
        if (p < nK) {
            const uint32_t st = sm + p * STAGE_BYTES;
            cp_tile<128>(st,           Ah, lda, m0, p, tid);
            cp_tile<128>(st + A_PLANE, Al, lda, m0, p, tid);
            cp_tile<256>(st + BH_OFF,  Bh, ldb, n0, p, tid);
            cp_tile<256>(st + BL_OFF,  Bl, ldb, n0, p, tid);
        }
        CP_COMMIT();
    }

    for (int i = 0; i < nK; i++) {
        CP_WAIT(1);
        __syncthreads();

        const uint32_t stg = sm + (uint32_t)(i % NSTAGE) * STAGE_BYTES;
#pragma unroll
        for (int ks = 0; ks < 2; ks++) {
            const uint32_t aCh = (uint32_t)((ks * 2 + khA) ^ swA) << 4;
            const uint32_t bCh = (uint32_t)((ks * 2 + khB) ^ swB) << 4;
            uint32_t ah[4][4], al[4][4];
#pragma unroll
            for (int mt = 0; mt < 4; mt++) {
                LDSM_X4(ah[mt][0], ah[mt][1], ah[mt][2], ah[mt][3],
                        stg + aRow + mt * 1024 + aCh);
                LDSM_X4(al[mt][0], al[mt][1], al[mt][2], al[mt][3],
                        stg + A_PLANE + aRow + mt * 1024 + aCh);
            }
#pragma unroll
            for (int nt2 = 0; nt2 < 4; nt2++) {
                uint32_t bh[4], bl[4];
                LDSM_X4(bh[0], bh[1], bh[2], bh[3],
                        stg + BH_OFF + bRow + nt2 * 1024 + bCh);
                LDSM_X4(bl[0], bl[1], bl[2], bl[3],
                        stg + BL_OFF + bRow + nt2 * 1024 + bCh);
#pragma unroll
                for (int mt = 0; mt < 4; mt++)
#pragma unroll
                    for (int h = 0; h < 2; h++) {
                        float* d = acc[mt][nt2 * 2 + h];
                        mma16816(d, ah[mt], &bh[h * 2]);
                        mma16816(d, ah[mt], &bl[h * 2]);
                        mma16816(d, al[mt], &bh[h * 2]);
                    }
            }
        }

        // issue stage i+2 (readers of that buffer joined at this iter's sync)
        const int nx = i + 2;
        if (nx < nK) {
            const uint32_t st = sm + (uint32_t)(nx % NSTAGE) * STAGE_BYTES;
            cp_tile<128>(st,           Ah, lda, m0, nx, tid);
            cp_tile<128>(st + A_PLANE, Al, lda, m0, nx, tid);
            cp_tile<256>(st + BH_OFF,  Bh, ldb, n0, nx, tid);
            cp_tile<256>(st + BL_OFF,  Bl, ldb, n0, nx, tid);
        }
        CP_COMMIT();
    }
    __syncthreads();   // mainloop done; smem reusable below

    // ---- epilogue ----
    const int g  = lane >> 2;
    const int tg = lane & 3;
    float rsum[4][2];
    if (EPI == 3) {
#pragma unroll
        for (int mt = 0; mt < 4; mt++) { rsum[mt][0] = 0.f; rsum[mt][1] = 0.f; }
    }

#pragma unroll
    for (int mt = 0; mt < 4; mt++) {
        const int m = m0 + mW + mt * 16 + g;
        float bm0 = 0.f, bm8 = 0.f;
        if (EPI == 2) { bm0 = bias[m]; bm8 = bias[m + 8]; }
#pragma unroll
        for (int nt = 0; nt < 8; nt++) {
            const int n = n0 + nW + nt * 8 + tg * 2;
            float d0 = acc[mt][nt][0] * alpha;
            float d1 = acc[mt][nt][1] * alpha;
            float d2 = acc[mt][nt][2] * alpha;
            float d3 = acc[mt][nt][3] * alpha;
            if (EPI == 1) {
                float2 bb = *(const float2*)(bias + n);
                d0 += bb.x; d1 += bb.y; d2 += bb.x; d3 += bb.y;
            } else if (EPI == 2) {
                d0 += bm0; d1 += bm0; d2 += bm8; d3 += bm8;
            } else if (EPI == 3) {
                d0 = __expf(d0); d1 = __expf(d1); d2 = __expf(d2); d3 = __expf(d3);
                rsum[mt][0] += d0 + d1;
                rsum[mt][1] += d2 + d3;
            } else if (EPI == 4) {
                float2 iv = *(const float2*)(aux + (size_t)blockIdx.z * Sn + n);
                d0 *= iv.x; d1 *= iv.y; d2 *= iv.x; d3 *= iv.y;
            }
            if (EPI == 4) {
                float* C = (float*)Ch + (size_t)blockIdx.z * sC;
                float2 o0 = { d0, d1 };
                float2 o1 = { d2, d3 };
                *(float2*)(C + (size_t)m * ldc + n)       = o0;
                *(float2*)(C + (size_t)(m + 8) * ldc + n) = o1;
            } else {
                bf16 h0, l0, h1, l1, h2, l2, h3, l3;
                split_hl(d0, h0, l0); split_hl(d1, h1, l1);
                split_hl(d2, h2, l2); split_hl(d3, h3, l3);
                bf16* CH = (bf16*)Ch + (size_t)blockIdx.z * sC;
                bf16* CL = (bf16*)Cl + (size_t)blockIdx.z * sC;
                *(__nv_bfloat162*)(CH + (size_t)m * ldc + n)       = __nv_bfloat162(h0, h1);
                *(__nv_bfloat162*)(CH + (size_t)(m + 8) * ldc + n) = __nv_bfloat162(h2, h3);
                *(__nv_bfloat162*)(CL + (size_t)m * ldc + n)       = __nv_bfloat162(l0, l1);
                *(__nv_bfloat162*)(CL + (size_t)(m + 8) * ldc + n) = __nv_bfloat162(l2, l3);
            }
        }
    }

    if (EPI == 3) {
        // reduce partial row sums: across tg lanes, then across the 4 n-warps
#pragma unroll
        for (int mt = 0; mt < 4; mt++) {
#pragma unroll
            for (int h = 0; h < 2; h++) {
                float s = rsum[mt][h];
                s += __shfl_xor_sync(0xffffffffu, s, 1);
                s += __shfl_xor_sync(0xffffffffu, s, 2);
                rsum[mt][h] = s;
            }
        }
        float* ss = (float*)smem;               // [4 n-warps][128 rows]
        const int nWj = wid & 3;
        if (tg == 0) {
#pragma unroll
            for (int mt = 0; mt < 4; mt++) {
                ss[nWj * 128 + mW + mt * 16 + g]     = rsum[mt][0];
                ss[nWj * 128 + mW + mt * 16 + 8 + g] = rsum[mt][1];
            }
        }
        __syncthreads();
        if (tid < 128) {
            float t = ss[tid] + ss[128 + tid] + ss[256 + tid] + ss[384 + tid];
            aux[((size_t)blockIdx.z * 8 + blockIdx.x) * Sn + m0 + tid] = t;
        }
    }
}

// ---------------- converters --------------------------------------------------
__global__ void __launch_bounds__(256)
xpose_pack(const float* __restrict__ x, bf16* __restrict__ xh, bf16* __restrict__ xl)
{
    __shared__ float t[32][33];
    const int tx = threadIdx.x, ty = threadIdx.y;
    const int s0 = blockIdx.x * 32, c0 = blockIdx.y * 32;
    const size_t bi = (size_t)blockIdx.z * Cin * Sn;
    const size_t bo = (size_t)blockIdx.z * Sn * Cin;
#pragma unroll
    for (int j = ty; j < 32; j += 8)
        t[j][tx] = x[bi + (size_t)(c0 + j) * Sn + s0 + tx];
    __syncthreads();
#pragma unroll
    for (int j = ty; j < 32; j += 8) {
        bf16 h, l;
        split_hl(t[tx][j], h, l);
        xh[bo + (size_t)(s0 + j) * Cin + c0 + tx] = h;
        xl[bo + (size_t)(s0 + j) * Cin + c0 + tx] = l;
    }
}

__global__ void __launch_bounds__(256)
pack_f32(const float* __restrict__ in, bf16* __restrict__ oh, bf16* __restrict__ ol, int n4)
{
    int i = blockIdx.x * 256 + threadIdx.x;
    if (i < n4) {
        float4 v = ((const float4*)in)[i];
        bf16 h0, l0, h1, l1, h2, l2, h3, l3;
        split_hl(v.x, h0, l0); split_hl(v.y, h1, l1);
        split_hl(v.z, h2, l2); split_hl(v.w, h3, l3);
        uint2 ho, lo;
        ho.x = (uint32_t)__bfloat16_as_ushort(h0) | ((uint32_t)__bfloat16_as_ushort(h1) << 16);
        ho.y = (uint32_t)__bfloat16_as_ushort(h2) | ((uint32_t)__bfloat16_as_ushort(h3) << 16);
        lo.x = (uint32_t)__bfloat16_as_ushort(l0) | ((uint32_t)__bfloat16_as_ushort(l1) << 16);
        lo.y = (uint32_t)__bfloat16_as_ushort(l2) | ((uint32_t)__bfloat16_as_ushort(l3) << 16);
        ((uint2*)oh)[i] = ho;
        ((uint2*)ol)[i] = lo;
    }
}

// rowsum over the 8 n-tiles -> reciprocal
__global__ void __launch_bounds__(256)
reduce_inv(const float* __restrict__ psum, float* __restrict__ inv)
{
    int i = blockIdx.x * 256 + threadIdx.x;     // over Bn*Sn
    int b = i >> 11, s = i & 2047;
    const float* p = psum + (size_t)b * 8 * Sn + s;
    float t = 0.f;
#pragma unroll
    for (int j = 0; j < 8; j++) t += p[(size_t)j * Sn];
    inv[i] = 1.0f / t;
}

// -----------------------------------------------------------------------------
extern "C" void kernel_launch(void* const* d_in, const int* in_sizes, int n_in,
                              void* d_out, int out_size)
{
    (void)in_sizes; (void)n_in; (void)out_size;
    const float* x  = (const float*)d_in[0];
    const float* wq = (const float*)d_in[1];
    const float* bq = (const float*)d_in[2];
    const float* wk = (const float*)d_in[3];
    const float* bk = (const float*)d_in[4];
    const float* wv = (const float*)d_in[5];
    const float* bv = (const float*)d_in[6];
    float* out = (float*)d_out;

    bf16 *xh, *xl, *wqkh, *wqkl, *wvh, *wvl, *qkh, *qkl, *vh, *vl, *eh, *el;
    float *bqk, *psum, *inv;
    cudaGetSymbolAddress((void**)&xh,   g_xT_h);  cudaGetSymbolAddress((void**)&xl,   g_xT_l);
    cudaGetSymbolAddress((void**)&wqkh, g_wqk_h); cudaGetSymbolAddress((void**)&wqkl, g_wqk_l);
    cudaGetSymbolAddress((void**)&wvh,  g_wv_h);  cudaGetSymbolAddress((void**)&wvl,  g_wv_l);
    cudaGetSymbolAddress((void**)&bqk,  g_bqk);
    cudaGetSymbolAddress((void**)&qkh,  g_qk_h);  cudaGetSymbolAddress((void**)&qkl,  g_qk_l);
    cudaGetSymbolAddress((void**)&vh,   g_v_h);   cudaGetSymbolAddress((void**)&vl,   g_v_l);
    cudaGetSymbolAddress((void**)&eh,   g_e_h);   cudaGetSymbolAddress((void**)&el,   g_e_l);
    cudaGetSymbolAddress((void**)&psum, g_psum);  cudaGetSymbolAddress((void**)&inv,  g_inv);

    cudaFuncSetAttribute(gemm_mma<1>, cudaFuncAttributeMaxDynamicSharedMemorySize, SM_TOTAL);
    cudaFuncSetAttribute(gemm_mma<2>, cudaFuncAttributeMaxDynamicSharedMemorySize, SM_TOTAL);
    cudaFuncSetAttribute(gemm_mma<3>, cudaFuncAttributeMaxDynamicSharedMemorySize, SM_TOTAL);
    cudaFuncSetAttribute(gemm_mma<4>, cudaFuncAttributeMaxDynamicSharedMemorySize, SM_TOTAL);

    // ---- conversions ----
    xpose_pack<<<dim3(Sn / 32, Cin / 32, Bn), dim3(32, 8)>>>(x, xh, xl);
    pack_f32<<<(KD * Cin / 4 + 255) / 256, 256>>>(wq, wqkh, wqkl, KD * Cin / 4);
    pack_f32<<<(KD * Cin / 4 + 255) / 256, 256>>>(wk, wqkh + (size_t)KD * Cin,
                                                  wqkl + (size_t)KD * Cin, KD * Cin / 4);
    pack_f32<<<(OD * Cin / 4 + 255) / 256, 256>>>(wv, wvh, wvl, OD * Cin / 4);
    cudaMemcpyAsync(bqk,      bq, KD * sizeof(float), cudaMemcpyDeviceToDevice, 0);
    cudaMemcpyAsync(bqk + KD, bk, KD * sizeof(float), cudaMemcpyDeviceToDevice, 0);

    const size_t sxT = (size_t)Sn * Cin;
    const size_t sqk = (size_t)Sn * QKN;
    const size_t sv  = (size_t)OD * Sn;
    const size_t ssc = (size_t)Sn * Sn;

    // qk = xT @ [Wq|Wk]^T + [bq|bk] -> (B,S,1024)   [m=s, n=qk-ch, k=c]
    gemm_mma<1><<<dim3(QKN / 256, Sn / 128, Bn), 256, SM_TOTAL>>>(
        xh, xl, wqkh, wqkl, bqk, nullptr, qkh, qkl,
        Cin, Cin, QKN, Cin / 32, sxT, 0, sqk, 1.0f);

    // v = Wv @ x + bv -> (B,OD,S)   [m=o, n=s, k=c]
    gemm_mma<2><<<dim3(Sn / 256, OD / 128, Bn), 256, SM_TOTAL>>>(
        wvh, wvl, xh, xl, bv, nullptr, vh, vl,
        Cin, Cin, Sn, Cin / 32, 0, sxT, sv, 1.0f);

    // E = exp(q @ k^T / sqrt(KD)) -> planes + partial row sums   [m=s, n=t, k=kd]
    gemm_mma<3><<<dim3(Sn / 256, Sn / 128, Bn), 256, SM_TOTAL>>>(
        qkh, qkl, qkh + KD, qkl + KD, nullptr, psum, eh, el,
        QKN, QKN, Sn, KD / 32, sqk, sqk, ssc, 0.04419417382415922f);

    // inv rowsums
    reduce_inv<<<Bn * Sn / 256, 256>>>(psum, inv);

    // out = (v @ E^T) * inv[s] -> (B,OD,S) fp32 into d_out   [m=o, n=s, k=t]
    gemm_mma<4><<<dim3(Sn / 256, OD / 128, Bn), 256, SM_TOTAL>>>(
        vh, vl, eh, el, nullptr, inv, out, nullptr,
        Sn, Sn, Sn, Sn / 32, sv, ssc, sv, 1.0f);
}

// round 9
// speedup vs baseline: 1.3756x; 1.3237x over previous
#include <cuda_runtime.h>
#include <cuda_bf16.h>
#include <cuda_fp16.h>
#include <cstdint>
#include <math.h>

#define Bn  8
#define Cin 1024
#define Sn  2048
#define KD  512
#define OD  1024
#define QKN 1024   // merged q|k output width

typedef __nv_bfloat16 bf16;

// ---------------- scratch ----------------------------------------------------
__device__ __align__(128) bf16   g_xT_h[(size_t)Bn * Sn * Cin];
__device__ __align__(128) bf16   g_xT_l[(size_t)Bn * Sn * Cin];
__device__ __align__(128) bf16   g_wqk_h[(size_t)QKN * Cin];
__device__ __align__(128) bf16   g_wqk_l[(size_t)QKN * Cin];
__device__ __align__(128) bf16   g_wv_h[(size_t)OD * Cin];
__device__ __align__(128) bf16   g_wv_l[(size_t)OD * Cin];
__device__ __align__(128) float  g_bqk[QKN];
__device__ __align__(128) bf16   g_qk_h[(size_t)Bn * Sn * QKN]; // q cols 0-511, k 512-1023
__device__ __align__(128) bf16   g_qk_l[(size_t)Bn * Sn * QKN];
__device__ __align__(128) __half g_v_h[(size_t)Bn * OD * Sn];   // v fp16 hi
__device__ __align__(128) __half g_v_l[(size_t)Bn * OD * Sn];   // v fp16 lo
__device__ __align__(128) __half g_e [(size_t)Bn * Sn * Sn];    // exp(scores), fp16 single
__device__ __align__(128) float  g_psum[(size_t)Bn * 16 * Sn];  // partial row sums
__device__ __align__(128) float  g_inv[(size_t)Bn * Sn];        // 1/rowsum

// ---------------- helpers ----------------------------------------------------
__device__ __forceinline__ uint32_t smem_u32(const void* p) {
    uint32_t a;
    asm("{ .reg .u64 t; cvta.to.shared.u64 t, %1; cvt.u32.u64 %0, t; }" : "=r"(a) : "l"(p));
    return a;
}

__device__ __forceinline__ void split_hl(float v, bf16& h, bf16& l) {
    h = __float2bfloat16(v);
    l = __float2bfloat16(v - __bfloat162float(h));
}

__device__ __forceinline__ void split_hl_f16(float v, __half& h, __half& l) {
    h = __float2half(v);
    l = __float2half(v - __half2float(h));
}

#define LDSM_X4(r0, r1, r2, r3, addr) \
    asm volatile("ldmatrix.sync.aligned.m8n8.x4.shared.b16 {%0,%1,%2,%3}, [%4];" \
                 : "=r"(r0), "=r"(r1), "=r"(r2), "=r"(r3) : "r"(addr))

__device__ __forceinline__ void mma16816(float* d, const uint32_t* a, const uint32_t* b) {
    asm volatile(
        "mma.sync.aligned.m16n8k16.row.col.f32.bf16.bf16.f32 "
        "{%0,%1,%2,%3}, {%4,%5,%6,%7}, {%8,%9}, {%0,%1,%2,%3};"
        : "+f"(d[0]), "+f"(d[1]), "+f"(d[2]), "+f"(d[3])
        : "r"(a[0]), "r"(a[1]), "r"(a[2]), "r"(a[3]), "r"(b[0]), "r"(b[1]));
}

__device__ __forceinline__ void mma16816h(float* d, const uint32_t* a, const uint32_t* b) {
    asm volatile(
        "mma.sync.aligned.m16n8k16.row.col.f32.f16.f16.f32 "
        "{%0,%1,%2,%3}, {%4,%5,%6,%7}, {%8,%9}, {%0,%1,%2,%3};"
        : "+f"(d[0]), "+f"(d[1]), "+f"(d[2]), "+f"(d[3])
        : "r"(a[0]), "r"(a[1]), "r"(a[2]), "r"(a[3]), "r"(b[0]), "r"(b[1]));
}

#define CP_ASYNC16(dst, src) \
    asm volatile("cp.async.cg.shared.global [%0], [%1], 16;" :: "r"(dst), "l"(src) : "memory")
#define CP_COMMIT()  asm volatile("cp.async.commit_group;" ::: "memory")
#define CP_WAIT(n)   asm volatile("cp.async.wait_group %0;" :: "n"(n) : "memory")

// tile: 128 rows x 32 elems (2B each -> 64B rows); 16B-chunk swizzle c4 ^= (row>>1)&3
template<typename T>
__device__ __forceinline__ void cp_tile(uint32_t sdst, const T* __restrict__ g,
                                        int ld, int row0, int kc, int tid) {
#pragma unroll
    for (int it = 0; it < 2; it++) {
        int slot = tid + it * 256;
        int row  = slot >> 2;
        int c4   = slot & 3;
        uint32_t off = (uint32_t)row * 64 + (uint32_t)((c4 ^ ((row >> 1) & 3)) << 4);
        CP_ASYNC16(sdst + off, g + (size_t)(row0 + row) * ld + kc * 32 + c4 * 8);
    }
}

// ================= bf16x3 GEMM (projections + scores), R5 structure =========
// EPI: 1 = +bias[n], bf16 HL out          (qk projection)
//      2 = +bias[m], fp16 HL out          (v projection)
//      3 = exp(d) -> fp16 single plane + renormalized psum (scores)
#define STAGE_BYTES 32768
#define NSTAGE      3
#define SM_TOTAL    (NSTAGE * STAGE_BYTES)

template<int EPI>
__global__ void __launch_bounds__(256)
gemm_mma(const bf16* __restrict__ Ah, const bf16* __restrict__ Al,
         const bf16* __restrict__ Bh, const bf16* __restrict__ Bl,
         const float* __restrict__ bias, float* __restrict__ aux,
         void* __restrict__ Ch, void* __restrict__ Cl,
         int lda, int ldb, int ldc, int nK,
         size_t sA, size_t sB, size_t sC, float alpha)
{
    extern __shared__ __align__(1024) char smem[];
    const uint32_t sm = smem_u32(smem);
    const int tid  = threadIdx.x;
    const int lane = tid & 31;
    const int wid  = tid >> 5;
    const int m0   = blockIdx.y * 128;
    const int n0   = blockIdx.x * 128;
    const int mW   = (wid >> 2) * 64;
    const int nW   = (wid & 3) * 32;

    Ah += (size_t)blockIdx.z * sA;  Al += (size_t)blockIdx.z * sA;
    Bh += (size_t)blockIdx.z * sB;  Bl += (size_t)blockIdx.z * sB;

    float acc[4][4][4];
#pragma unroll
    for (int i = 0; i < 4; i++)
#pragma unroll
        for (int j = 0; j < 4; j++) {
            acc[i][j][0] = 0.f; acc[i][j][1] = 0.f; acc[i][j][2] = 0.f; acc[i][j][3] = 0.f;
        }

    const uint32_t rl   = lane & 15;
    const uint32_t khA  = lane >> 4;
    const uint32_t swA  = (rl >> 1) & 3;
    const uint32_t aRow = (uint32_t)(mW + rl) * 64;
    const uint32_t rnl  = ((lane >> 4) << 3) | (lane & 7);
    const uint32_t khB  = (lane >> 3) & 1;
    const uint32_t swB  = (rnl >> 1) & 3;
    const uint32_t bRow = (uint32_t)(nW + rnl) * 64;

    // prologue: stages 0, 1
#pragma unroll
    for (int p = 0; p < 2; p++) {
        if (p < nK) {
            const uint32_t st = sm + p * STAGE_BYTES;
            cp_tile(st,         Ah, lda, m0, p, tid);
            cp_tile(st + 8192,  Al, lda, m0, p, tid);
            cp_tile(st + 16384, Bh, ldb, n0, p, tid);
            cp_tile(st + 24576, Bl, ldb, n0, p, tid);
        }
        CP_COMMIT();
    }

    for (int i = 0; i < nK; i++) {
        CP_WAIT(1);
        __syncthreads();

        const uint32_t stg = sm + (uint32_t)(i % NSTAGE) * STAGE_BYTES;
#pragma unroll
        for (int ks = 0; ks < 2; ks++) {
            const uint32_t aCh = (uint32_t)((ks * 2 + khA) ^ swA) << 4;
            const uint32_t bCh = (uint32_t)((ks * 2 + khB) ^ swB) << 4;
            uint32_t ah[4][4], al[4][4], bh[8], bl[8];
#pragma unroll
            for (int mt = 0; mt < 4; mt++) {
                LDSM_X4(ah[mt][0], ah[mt][1], ah[mt][2], ah[mt][3],
                        stg + aRow + mt * 1024 + aCh);
                LDSM_X4(al[mt][0], al[mt][1], al[mt][2], al[mt][3],
                        stg + 8192 + aRow + mt * 1024 + aCh);
            }
            LDSM_X4(bh[0], bh[1], bh[2], bh[3], stg + 16384 + bRow + bCh);
            LDSM_X4(bh[4], bh[5], bh[6], bh[7], stg + 16384 + bRow + 1024 + bCh);
            LDSM_X4(bl[0], bl[1], bl[2], bl[3], stg + 24576 + bRow + bCh);
            LDSM_X4(bl[4], bl[5], bl[6], bl[7], stg + 24576 + bRow + 1024 + bCh);

#pragma unroll
            for (int mt = 0; mt < 4; mt++)
#pragma unroll
                for (int nt = 0; nt < 4; nt++) {
                    mma16816(acc[mt][nt], ah[mt], &bh[nt * 2]);
                    mma16816(acc[mt][nt], ah[mt], &bl[nt * 2]);
                    mma16816(acc[mt][nt], al[mt], &bh[nt * 2]);
                }
        }

        const int nx = i + 2;
        if (nx < nK) {
            const uint32_t st = sm + (uint32_t)(nx % NSTAGE) * STAGE_BYTES;
            cp_tile(st,         Ah, lda, m0, nx, tid);
            cp_tile(st + 8192,  Al, lda, m0, nx, tid);
            cp_tile(st + 16384, Bh, ldb, n0, nx, tid);
            cp_tile(st + 24576, Bl, ldb, n0, nx, tid);
        }
        CP_COMMIT();
    }
    __syncthreads();   // mainloop done; smem reusable below

    // ---- epilogue ----
    const int g  = lane >> 2;
    const int tg = lane & 3;
    float rsum[4][2];
    if (EPI == 3) {
#pragma unroll
        for (int mt = 0; mt < 4; mt++) { rsum[mt][0] = 0.f; rsum[mt][1] = 0.f; }
    }

#pragma unroll
    for (int mt = 0; mt < 4; mt++) {
        const int m = m0 + mW + mt * 16 + g;
        float bm0 = 0.f, bm8 = 0.f;
        if (EPI == 2) { bm0 = bias[m]; bm8 = bias[m + 8]; }
#pragma unroll
        for (int nt = 0; nt < 4; nt++) {
            const int n = n0 + nW + nt * 8 + tg * 2;
            float d0 = acc[mt][nt][0] * alpha;
            float d1 = acc[mt][nt][1] * alpha;
            float d2 = acc[mt][nt][2] * alpha;
            float d3 = acc[mt][nt][3] * alpha;
            if (EPI == 1) {
                float2 bb = *(const float2*)(bias + n);
                d0 += bb.x; d1 += bb.y; d2 += bb.x; d3 += bb.y;
                bf16 h0, l0, h1, l1, h2, l2, h3, l3;
                split_hl(d0, h0, l0); split_hl(d1, h1, l1);
                split_hl(d2, h2, l2); split_hl(d3, h3, l3);
                bf16* CH = (bf16*)Ch + (size_t)blockIdx.z * sC;
                bf16* CL = (bf16*)Cl + (size_t)blockIdx.z * sC;
                *(__nv_bfloat162*)(CH + (size_t)m * ldc + n)       = __nv_bfloat162(h0, h1);
                *(__nv_bfloat162*)(CH + (size_t)(m + 8) * ldc + n) = __nv_bfloat162(h2, h3);
                *(__nv_bfloat162*)(CL + (size_t)m * ldc + n)       = __nv_bfloat162(l0, l1);
                *(__nv_bfloat162*)(CL + (size_t)(m + 8) * ldc + n) = __nv_bfloat162(l2, l3);
            } else if (EPI == 2) {
                d0 += bm0; d1 += bm0; d2 += bm8; d3 += bm8;
                __half h0, l0, h1, l1, h2, l2, h3, l3;
                split_hl_f16(d0, h0, l0); split_hl_f16(d1, h1, l1);
                split_hl_f16(d2, h2, l2); split_hl_f16(d3, h3, l3);
                __half* CH = (__half*)Ch + (size_t)blockIdx.z * sC;
                __half* CL = (__half*)Cl + (size_t)blockIdx.z * sC;
                *(__half2*)(CH + (size_t)m * ldc + n)       = __halves2half2(h0, h1);
                *(__half2*)(CH + (size_t)(m + 8) * ldc + n) = __halves2half2(h2, h3);
                *(__half2*)(CL + (size_t)m * ldc + n)       = __halves2half2(l0, l1);
                *(__half2*)(CL + (size_t)(m + 8) * ldc + n) = __halves2half2(l2, l3);
            } else { // EPI == 3
                __half e0 = __float2half(__expf(d0));
                __half e1 = __float2half(__expf(d1));
                __half e2 = __float2half(__expf(d2));
                __half e3 = __float2half(__expf(d3));
                // accumulate the ROUNDED values so normalization is exact
                rsum[mt][0] += __half2float(e0) + __half2float(e1);
                rsum[mt][1] += __half2float(e2) + __half2float(e3);
                __half* CE = (__half*)Ch + (size_t)blockIdx.z * sC;
                *(__half2*)(CE + (size_t)m * ldc + n)       = __halves2half2(e0, e1);
                *(__half2*)(CE + (size_t)(m + 8) * ldc + n) = __halves2half2(e2, e3);
            }
        }
    }

    if (EPI == 3) {
#pragma unroll
        for (int mt = 0; mt < 4; mt++) {
#pragma unroll
            for (int h = 0; h < 2; h++) {
                float s = rsum[mt][h];
                s += __shfl_xor_sync(0xffffffffu, s, 1);
                s += __shfl_xor_sync(0xffffffffu, s, 2);
                rsum[mt][h] = s;
            }
        }
        float* ss = (float*)smem;               // [4 n-warps][128 rows]
        const int nWj = wid & 3;
        if (tg == 0) {
#pragma unroll
            for (int mt = 0; mt < 4; mt++) {
                ss[nWj * 128 + mW + mt * 16 + g]     = rsum[mt][0];
                ss[nWj * 128 + mW + mt * 16 + 8 + g] = rsum[mt][1];
            }
        }
        __syncthreads();
        if (tid < 128) {
            float t = ss[tid] + ss[128 + tid] + ss[256 + tid] + ss[384 + tid];
            aux[((size_t)blockIdx.z * 16 + blockIdx.x) * Sn + m0 + tid] = t;
        }
    }
}

// ================= fp16 PV GEMM: out = (v @ E^T) * inv[s] ====================
// A = v fp16 hi/lo (2 planes, K-major over t), B = E fp16 single plane.
// 2 MMAs per fragment pair. Stage = Ah 8K | Al 8K | B 8K = 24 KB.
#define PV_STAGE 24576
#define PV_SMEM  (NSTAGE * PV_STAGE)

__global__ void __launch_bounds__(256)
gemm_pv(const __half* __restrict__ Ah, const __half* __restrict__ Al,
        const __half* __restrict__ B,
        const float* __restrict__ inv, float* __restrict__ C,
        int nK)
{
    extern __shared__ __align__(1024) char smem[];
    const uint32_t sm = smem_u32(smem);
    const int tid  = threadIdx.x;
    const int lane = tid & 31;
    const int wid  = tid >> 5;
    const int m0   = blockIdx.y * 128;     // o
    const int n0   = blockIdx.x * 128;     // s
    const int mW   = (wid >> 2) * 64;
    const int nW   = (wid & 3) * 32;

    Ah += (size_t)blockIdx.z * OD * Sn;
    Al += (size_t)blockIdx.z * OD * Sn;
    B  += (size_t)blockIdx.z * Sn * Sn;
    C  += (size_t)blockIdx.z * OD * Sn;

    float acc[4][4][4];
#pragma unroll
    for (int i = 0; i < 4; i++)
#pragma unroll
        for (int j = 0; j < 4; j++) {
            acc[i][j][0] = 0.f; acc[i][j][1] = 0.f; acc[i][j][2] = 0.f; acc[i][j][3] = 0.f;
        }

    const uint32_t rl   = lane & 15;
    const uint32_t khA  = lane >> 4;
    const uint32_t swA  = (rl >> 1) & 3;
    const uint32_t aRow = (uint32_t)(mW + rl) * 64;
    const uint32_t rnl  = ((lane >> 4) << 3) | (lane & 7);
    const uint32_t khB  = (lane >> 3) & 1;
    const uint32_t swB  = (rnl >> 1) & 3;
    const uint32_t bRow = (uint32_t)(nW + rnl) * 64;

#pragma unroll
    for (int p = 0; p < 2; p++) {
        if (p < nK) {
            const uint32_t st = sm + p * PV_STAGE;
            cp_tile(st,         Ah, Sn, m0, p, tid);
            cp_tile(st + 8192,  Al, Sn, m0, p, tid);
            cp_tile(st + 16384, B,  Sn, n0, p, tid);
        }
        CP_COMMIT();
    }

    for (int i = 0; i < nK; i++) {
        CP_WAIT(1);
        __syncthreads();

        const uint32_t stg = sm + (uint32_t)(i % NSTAGE) * PV_STAGE;
#pragma unroll
        for (int ks = 0; ks < 2; ks++) {
            const uint32_t aCh = (uint32_t)((ks * 2 + khA) ^ swA) << 4;
            const uint32_t bCh = (uint32_t)((ks * 2 + khB) ^ swB) << 4;
            uint32_t ah[4][4], al[4][4], bh[8];
#pragma unroll
            for (int mt = 0; mt < 4; mt++) {
                LDSM_X4(ah[mt][0], ah[mt][1], ah[mt][2], ah[mt][3],
                        stg + aRow + mt * 1024 + aCh);
                LDSM_X4(al[mt][0], al[mt][1], al[mt][2], al[mt][3],
                        stg + 8192 + aRow + mt * 1024 + aCh);
            }
            LDSM_X4(bh[0], bh[1], bh[2], bh[3], stg + 16384 + bRow + bCh);
            LDSM_X4(bh[4], bh[5], bh[6], bh[7], stg + 16384 + bRow + 1024 + bCh);

#pragma unroll
            for (int mt = 0; mt < 4; mt++)
#pragma unroll
                for (int nt = 0; nt < 4; nt++) {
                    mma16816h(acc[mt][nt], ah[mt], &bh[nt * 2]);
                    mma16816h(acc[mt][nt], al[mt], &bh[nt * 2]);
                }
        }

        const int nx = i + 2;
        if (nx < nK) {
            const uint32_t st = sm + (uint32_t)(nx % NSTAGE) * PV_STAGE;
            cp_tile(st,         Ah, Sn, m0, nx, tid);
            cp_tile(st + 8192,  Al, Sn, m0, nx, tid);
            cp_tile(st + 16384, B,  Sn, n0, nx, tid);
        }
        CP_COMMIT();
    }

    // ---- epilogue: scale by inv[s], write fp32 ----
    const int g  = lane >> 2;
    const int tg = lane & 3;
#pragma unroll
    for (int mt = 0; mt < 4; mt++) {
        const int m = m0 + mW + mt * 16 + g;
#pragma unroll
        for (int nt = 0; nt < 4; nt++) {
            const int n = n0 + nW + nt * 8 + tg * 2;
            float2 iv = *(const float2*)(inv + (size_t)blockIdx.z * Sn + n);
            float2 o0 = { acc[mt][nt][0] * iv.x, acc[mt][nt][1] * iv.y };
            float2 o1 = { acc[mt][nt][2] * iv.x, acc[mt][nt][3] * iv.y };
            *(float2*)(C + (size_t)m * Sn + n)       = o0;
            *(float2*)(C + (size_t)(m + 8) * Sn + n) = o1;
        }
    }
}

// ---------------- converters --------------------------------------------------
__global__ void __launch_bounds__(256)
xpose_pack(const float* __restrict__ x, bf16* __restrict__ xh, bf16* __restrict__ xl)
{
    __shared__ float t[32][33];
    const int tx = threadIdx.x, ty = threadIdx.y;
    const int s0 = blockIdx.x * 32, c0 = blockIdx.y * 32;
    const size_t bi = (size_t)blockIdx.z * Cin * Sn;
    const size_t bo = (size_t)blockIdx.z * Sn * Cin;
#pragma unroll
    for (int j = ty; j < 32; j += 8)
        t[j][tx] = x[bi + (size_t)(c0 + j) * Sn + s0 + tx];
    __syncthreads();
#pragma unroll
    for (int j = ty; j < 32; j += 8) {
        bf16 h, l;
        split_hl(t[tx][j], h, l);
        xh[bo + (size_t)(s0 + j) * Cin + c0 + tx] = h;
        xl[bo + (size_t)(s0 + j) * Cin + c0 + tx] = l;
    }
}

__global__ void __launch_bounds__(256)
pack_f32(const float* __restrict__ in, bf16* __restrict__ oh, bf16* __restrict__ ol, int n4)
{
    int i = blockIdx.x * 256 + threadIdx.x;
    if (i < n4) {
        float4 v = ((const float4*)in)[i];
        bf16 h0, l0, h1, l1, h2, l2, h3, l3;
        split_hl(v.x, h0, l0); split_hl(v.y, h1, l1);
        split_hl(v.z, h2, l2); split_hl(v.w, h3, l3);
        uint2 ho, lo;
        ho.x = (uint32_t)__bfloat16_as_ushort(h0) | ((uint32_t)__bfloat16_as_ushort(h1) << 16);
        ho.y = (uint32_t)__bfloat16_as_ushort(h2) | ((uint32_t)__bfloat16_as_ushort(h3) << 16);
        lo.x = (uint32_t)__bfloat16_as_ushort(l0) | ((uint32_t)__bfloat16_as_ushort(l1) << 16);
        lo.y = (uint32_t)__bfloat16_as_ushort(l2) | ((uint32_t)__bfloat16_as_ushort(l3) << 16);
        ((uint2*)oh)[i] = ho;
        ((uint2*)ol)[i] = lo;
    }
}

// rowsum over the 16 n-tiles -> reciprocal
__global__ void __launch_bounds__(256)
reduce_inv(const float* __restrict__ psum, float* __restrict__ inv)
{
    int i = blockIdx.x * 256 + threadIdx.x;     // over Bn*Sn
    int b = i >> 11, s = i & 2047;
    const float* p = psum + (size_t)b * 16 * Sn + s;
    float t = 0.f;
#pragma unroll
    for (int j = 0; j < 16; j++) t += p[(size_t)j * Sn];
    inv[i] = 1.0f / t;
}

// -----------------------------------------------------------------------------
extern "C" void kernel_launch(void* const* d_in, const int* in_sizes, int n_in,
                              void* d_out, int out_size)
{
    (void)in_sizes; (void)n_in; (void)out_size;
    const float* x  = (const float*)d_in[0];
    const float* wq = (const float*)d_in[1];
    const float* bq = (const float*)d_in[2];
    const float* wk = (const float*)d_in[3];
    const float* bk = (const float*)d_in[4];
    const float* wv = (const float*)d_in[5];
    const float* bv = (const float*)d_in[6];
    float* out = (float*)d_out;

    bf16 *xh, *xl, *wqkh, *wqkl, *wvh, *wvl, *qkh, *qkl;
    __half *vh, *vl, *eP;
    float *bqk, *psum, *inv;
    cudaGetSymbolAddress((void**)&xh,   g_xT_h);  cudaGetSymbolAddress((void**)&xl,   g_xT_l);
    cudaGetSymbolAddress((void**)&wqkh, g_wqk_h); cudaGetSymbolAddress((void**)&wqkl, g_wqk_l);
    cudaGetSymbolAddress((void**)&wvh,  g_wv_h);  cudaGetSymbolAddress((void**)&wvl,  g_wv_l);
    cudaGetSymbolAddress((void**)&bqk,  g_bqk);
    cudaGetSymbolAddress((void**)&qkh,  g_qk_h);  cudaGetSymbolAddress((void**)&qkl,  g_qk_l);
    cudaGetSymbolAddress((void**)&vh,   g_v_h);   cudaGetSymbolAddress((void**)&vl,   g_v_l);
    cudaGetSymbolAddress((void**)&eP,   g_e);
    cudaGetSymbolAddress((void**)&psum, g_psum);  cudaGetSymbolAddress((void**)&inv,  g_inv);

    cudaFuncSetAttribute(gemm_mma<1>, cudaFuncAttributeMaxDynamicSharedMemorySize, SM_TOTAL);
    cudaFuncSetAttribute(gemm_mma<2>, cudaFuncAttributeMaxDynamicSharedMemorySize, SM_TOTAL);
    cudaFuncSetAttribute(gemm_mma<3>, cudaFuncAttributeMaxDynamicSharedMemorySize, SM_TOTAL);
    cudaFuncSetAttribute(gemm_pv,     cudaFuncAttributeMaxDynamicSharedMemorySize, PV_SMEM);

    // ---- conversions ----
    xpose_pack<<<dim3(Sn / 32, Cin / 32, Bn), dim3(32, 8)>>>(x, xh, xl);
    pack_f32<<<(KD * Cin / 4 + 255) / 256, 256>>>(wq, wqkh, wqkl, KD * Cin / 4);
    pack_f32<<<(KD * Cin / 4 + 255) / 256, 256>>>(wk, wqkh + (size_t)KD * Cin,
                                                  wqkl + (size_t)KD * Cin, KD * Cin / 4);
    pack_f32<<<(OD * Cin / 4 + 255) / 256, 256>>>(wv, wvh, wvl, OD * Cin / 4);
    cudaMemcpyAsync(bqk,      bq, KD * sizeof(float), cudaMemcpyDeviceToDevice, 0);
    cudaMemcpyAsync(bqk + KD, bk, KD * sizeof(float), cudaMemcpyDeviceToDevice, 0);

    const size_t sxT = (size_t)Sn * Cin;
    const size_t sqk = (size_t)Sn * QKN;
    const size_t sv  = (size_t)OD * Sn;
    const size_t ssc = (size_t)Sn * Sn;

    // qk = xT @ [Wq|Wk]^T + [bq|bk] -> (B,S,1024) bf16 HL  [m=s, n=qk-ch, k=c]
    gemm_mma<1><<<dim3(QKN / 128, Sn / 128, Bn), 256, SM_TOTAL>>>(
        xh, xl, wqkh, wqkl, bqk, nullptr, qkh, qkl,
        Cin, Cin, QKN, Cin / 32, sxT, 0, sqk, 1.0f);

    // v = Wv @ x + bv -> (B,OD,S) fp16 HL   [m=o, n=s, k=c]
    gemm_mma<2><<<dim3(Sn / 128, OD / 128, Bn), 256, SM_TOTAL>>>(
        wvh, wvl, xh, xl, bv, nullptr, vh, vl,
        Cin, Cin, Sn, Cin / 32, 0, sxT, sv, 1.0f);

    // E = exp(q @ k^T / sqrt(KD)) -> fp16 single plane + renormalized psum
    gemm_mma<3><<<dim3(Sn / 128, Sn / 128, Bn), 256, SM_TOTAL>>>(
        qkh, qkl, qkh + KD, qkl + KD, nullptr, psum, eP, nullptr,
        QKN, QKN, Sn, KD / 32, sqk, sqk, ssc, 0.04419417382415922f);

    // inv rowsums
    reduce_inv<<<Bn * Sn / 256, 256>>>(psum, inv);

    // out = (v @ E^T) * inv[s] -> (B,OD,S) fp32 into d_out
    gemm_pv<<<dim3(Sn / 128, OD / 128, Bn), 256, PV_SMEM>>>(
        vh, vl, eP, inv, out, Sn / 32);
}

// round 10
// speedup vs baseline: 1.5882x; 1.1546x over previous
#include <cuda_runtime.h>
#include <cuda_bf16.h>
#include <cuda_fp16.h>
#include <cstdint>
#include <math.h>

#define Bn  8
#define Cin 1024
#define Sn  2048
#define KD  512
#define OD  1024
#define QKN 1024   // merged q|k output width

typedef __nv_bfloat16 bf16;

// ---------------- scratch ----------------------------------------------------
__device__ __align__(128) bf16   g_xT_h[(size_t)Bn * Sn * Cin];
__device__ __align__(128) bf16   g_xT_l[(size_t)Bn * Sn * Cin];
__device__ __align__(128) bf16   g_wqk_h[(size_t)QKN * Cin];
__device__ __align__(128) bf16   g_wqk_l[(size_t)QKN * Cin];
__device__ __align__(128) bf16   g_wv_h[(size_t)OD * Cin];
__device__ __align__(128) bf16   g_wv_l[(size_t)OD * Cin];
__device__ __align__(128) float  g_bqk[QKN];
__device__ __align__(128) bf16   g_q_h[(size_t)Bn * Sn * KD];   // q bf16 hi ONLY
__device__ __align__(128) bf16   g_k_h[(size_t)Bn * Sn * KD];   // k bf16 hi
__device__ __align__(128) bf16   g_k_l[(size_t)Bn * Sn * KD];   // k bf16 lo
__device__ __align__(128) __half g_v_h[(size_t)Bn * OD * Sn];   // v fp16 hi
__device__ __align__(128) __half g_v_l[(size_t)Bn * OD * Sn];   // v fp16 lo
__device__ __align__(128) __half g_e [(size_t)Bn * Sn * Sn];    // exp(scores), fp16
__device__ __align__(128) float  g_psum[(size_t)Bn * 16 * Sn];
__device__ __align__(128) float  g_inv[(size_t)Bn * Sn];

// ---------------- helpers ----------------------------------------------------
__device__ __forceinline__ uint32_t smem_u32(const void* p) {
    uint32_t a;
    asm("{ .reg .u64 t; cvta.to.shared.u64 t, %1; cvt.u32.u64 %0, t; }" : "=r"(a) : "l"(p));
    return a;
}

__device__ __forceinline__ void split_hl(float v, bf16& h, bf16& l) {
    h = __float2bfloat16(v);
    l = __float2bfloat16(v - __bfloat162float(h));
}

__device__ __forceinline__ void split_hl_f16(float v, __half& h, __half& l) {
    h = __float2half(v);
    l = __float2half(v - __half2float(h));
}

#define LDSM_X4(r0, r1, r2, r3, addr) \
    asm volatile("ldmatrix.sync.aligned.m8n8.x4.shared.b16 {%0,%1,%2,%3}, [%4];" \
                 : "=r"(r0), "=r"(r1), "=r"(r2), "=r"(r3) : "r"(addr))

__device__ __forceinline__ void mma16816(float* d, const uint32_t* a, const uint32_t* b) {
    asm volatile(
        "mma.sync.aligned.m16n8k16.row.col.f32.bf16.bf16.f32 "
        "{%0,%1,%2,%3}, {%4,%5,%6,%7}, {%8,%9}, {%0,%1,%2,%3};"
        : "+f"(d[0]), "+f"(d[1]), "+f"(d[2]), "+f"(d[3])
        : "r"(a[0]), "r"(a[1]), "r"(a[2]), "r"(a[3]), "r"(b[0]), "r"(b[1]));
}

__device__ __forceinline__ void mma16816h(float* d, const uint32_t* a, const uint32_t* b) {
    asm volatile(
        "mma.sync.aligned.m16n8k16.row.col.f32.f16.f16.f32 "
        "{%0,%1,%2,%3}, {%4,%5,%6,%7}, {%8,%9}, {%0,%1,%2,%3};"
        : "+f"(d[0]), "+f"(d[1]), "+f"(d[2]), "+f"(d[3])
        : "r"(a[0]), "r"(a[1]), "r"(a[2]), "r"(a[3]), "r"(b[0]), "r"(b[1]));
}

#define CP_ASYNC16(dst, src) \
    asm volatile("cp.async.cg.shared.global [%0], [%1], 16;" :: "r"(dst), "l"(src) : "memory")
#define CP_COMMIT()  asm volatile("cp.async.commit_group;" ::: "memory")
#define CP_WAIT(n)   asm volatile("cp.async.wait_group %0;" :: "n"(n) : "memory")

// tile: 128 rows x 32 elems (2B -> 64B rows); 16B-chunk swizzle c4 ^= (row>>1)&3
template<typename T>
__device__ __forceinline__ void cp_tile(uint32_t sdst, const T* __restrict__ g,
                                        int ld, int row0, int kc, int tid) {
#pragma unroll
    for (int it = 0; it < 2; it++) {
        int slot = tid + it * 256;
        int row  = slot >> 2;
        int c4   = slot & 3;
        uint32_t off = (uint32_t)row * 64 + (uint32_t)((c4 ^ ((row >> 1) & 3)) << 4);
        CP_ASYNC16(sdst + off, g + (size_t)(row0 + row) * ld + kc * 32 + c4 * 8);
    }
}

#define NSTAGE 3

// ================= 2-MMA bf16 GEMM: D = alpha*(A_hi . (Bh+Bl)) ===============
// EPI 1: +bias[n]; n<KD -> store q bf16 hi only; n>=KD -> store k hi/lo (qk proj)
// EPI 3: exp(d) -> fp16 E plane + renormalized psum                  (scores)
#define STAGE2 24576
#define SMEM2  (NSTAGE * STAGE2)

template<int EPI>
__global__ void __launch_bounds__(256)
gemm2(const bf16* __restrict__ A,
      const bf16* __restrict__ Bh, const bf16* __restrict__ Bl,
      const float* __restrict__ bias, float* __restrict__ aux,
      void* __restrict__ C0, void* __restrict__ C1, void* __restrict__ C2,
      int lda, int ldb, int ldc, int nK,
      size_t sA, size_t sB, size_t sC, float alpha)
{
    extern __shared__ __align__(1024) char smem[];
    const uint32_t sm = smem_u32(smem);
    const int tid  = threadIdx.x;
    const int lane = tid & 31;
    const int wid  = tid >> 5;
    const int m0   = blockIdx.y * 128;
    const int n0   = blockIdx.x * 128;
    const int mW   = (wid >> 2) * 64;
    const int nW   = (wid & 3) * 32;

    A  += (size_t)blockIdx.z * sA;
    Bh += (size_t)blockIdx.z * sB;  Bl += (size_t)blockIdx.z * sB;

    float acc[4][4][4];
#pragma unroll
    for (int i = 0; i < 4; i++)
#pragma unroll
        for (int j = 0; j < 4; j++) {
            acc[i][j][0] = 0.f; acc[i][j][1] = 0.f; acc[i][j][2] = 0.f; acc[i][j][3] = 0.f;
        }

    const uint32_t rl   = lane & 15;
    const uint32_t khA  = lane >> 4;
    const uint32_t swA  = (rl >> 1) & 3;
    const uint32_t aRow = (uint32_t)(mW + rl) * 64;
    const uint32_t rnl  = ((lane >> 4) << 3) | (lane & 7);
    const uint32_t khB  = (lane >> 3) & 1;
    const uint32_t swB  = (rnl >> 1) & 3;
    const uint32_t bRow = (uint32_t)(nW + rnl) * 64;

#pragma unroll
    for (int p = 0; p < 2; p++) {
        if (p < nK) {
            const uint32_t st = sm + p * STAGE2;
            cp_tile(st,         A,  lda, m0, p, tid);
            cp_tile(st + 8192,  Bh, ldb, n0, p, tid);
            cp_tile(st + 16384, Bl, ldb, n0, p, tid);
        }
        CP_COMMIT();
    }

    for (int i = 0; i < nK; i++) {
        CP_WAIT(1);
        __syncthreads();

        const uint32_t stg = sm + (uint32_t)(i % NSTAGE) * STAGE2;
#pragma unroll
        for (int ks = 0; ks < 2; ks++) {
            const uint32_t aCh = (uint32_t)((ks * 2 + khA) ^ swA) << 4;
            const uint32_t bCh = (uint32_t)((ks * 2 + khB) ^ swB) << 4;
            uint32_t ah[4][4], bh[8], bl[8];
#pragma unroll
            for (int mt = 0; mt < 4; mt++) {
                LDSM_X4(ah[mt][0], ah[mt][1], ah[mt][2], ah[mt][3],
                        stg + aRow + mt * 1024 + aCh);
            }
            LDSM_X4(bh[0], bh[1], bh[2], bh[3], stg + 8192 + bRow + bCh);
            LDSM_X4(bh[4], bh[5], bh[6], bh[7], stg + 8192 + bRow + 1024 + bCh);
            LDSM_X4(bl[0], bl[1], bl[2], bl[3], stg + 16384 + bRow + bCh);
            LDSM_X4(bl[4], bl[5], bl[6], bl[7], stg + 16384 + bRow + 1024 + bCh);

#pragma unroll
            for (int mt = 0; mt < 4; mt++)
#pragma unroll
                for (int nt = 0; nt < 4; nt++) {
                    mma16816(acc[mt][nt], ah[mt], &bh[nt * 2]);
                    mma16816(acc[mt][nt], ah[mt], &bl[nt * 2]);
                }
        }

        const int nx = i + 2;
        if (nx < nK) {
            const uint32_t st = sm + (uint32_t)(nx % NSTAGE) * STAGE2;
            cp_tile(st,         A,  lda, m0, nx, tid);
            cp_tile(st + 8192,  Bh, ldb, n0, nx, tid);
            cp_tile(st + 16384, Bl, ldb, n0, nx, tid);
        }
        CP_COMMIT();
    }
    __syncthreads();

    // ---- epilogue ----
    const int g  = lane >> 2;
    const int tg = lane & 3;
    float rsum[4][2];
    if (EPI == 3) {
#pragma unroll
        for (int mt = 0; mt < 4; mt++) { rsum[mt][0] = 0.f; rsum[mt][1] = 0.f; }
    }

#pragma unroll
    for (int mt = 0; mt < 4; mt++) {
        const int m = m0 + mW + mt * 16 + g;
#pragma unroll
        for (int nt = 0; nt < 4; nt++) {
            const int n = n0 + nW + nt * 8 + tg * 2;
            float d0 = acc[mt][nt][0] * alpha;
            float d1 = acc[mt][nt][1] * alpha;
            float d2 = acc[mt][nt][2] * alpha;
            float d3 = acc[mt][nt][3] * alpha;
            if (EPI == 1) {
                float2 bb = *(const float2*)(bias + n);
                d0 += bb.x; d1 += bb.y; d2 += bb.x; d3 += bb.y;
                if (n0 < KD) {
                    // q: hi plane only
                    bf16* Q = (bf16*)C0 + (size_t)blockIdx.z * sC;
                    __nv_bfloat162 h01(__float2bfloat16(d0), __float2bfloat16(d1));
                    __nv_bfloat162 h23(__float2bfloat16(d2), __float2bfloat16(d3));
                    *(__nv_bfloat162*)(Q + (size_t)m * ldc + n)       = h01;
                    *(__nv_bfloat162*)(Q + (size_t)(m + 8) * ldc + n) = h23;
                } else {
                    const int nk = n - KD;
                    bf16 h0, l0, h1, l1, h2, l2, h3, l3;
                    split_hl(d0, h0, l0); split_hl(d1, h1, l1);
                    split_hl(d2, h2, l2); split_hl(d3, h3, l3);
                    bf16* KH = (bf16*)C1 + (size_t)blockIdx.z * sC;
                    bf16* KL = (bf16*)C2 + (size_t)blockIdx.z * sC;
                    *(__nv_bfloat162*)(KH + (size_t)m * ldc + nk)       = __nv_bfloat162(h0, h1);
                    *(__nv_bfloat162*)(KH + (size_t)(m + 8) * ldc + nk) = __nv_bfloat162(h2, h3);
                    *(__nv_bfloat162*)(KL + (size_t)m * ldc + nk)       = __nv_bfloat162(l0, l1);
                    *(__nv_bfloat162*)(KL + (size_t)(m + 8) * ldc + nk) = __nv_bfloat162(l2, l3);
                }
            } else { // EPI == 3
                __half e0 = __float2half(__expf(d0));
                __half e1 = __float2half(__expf(d1));
                __half e2 = __float2half(__expf(d2));
                __half e3 = __float2half(__expf(d3));
                rsum[mt][0] += __half2float(e0) + __half2float(e1);
                rsum[mt][1] += __half2float(e2) + __half2float(e3);
                __half* CE = (__half*)C0 + (size_t)blockIdx.z * sC;
                *(__half2*)(CE + (size_t)m * ldc + n)       = __halves2half2(e0, e1);
                *(__half2*)(CE + (size_t)(m + 8) * ldc + n) = __halves2half2(e2, e3);
            }
        }
    }

    if (EPI == 3) {
#pragma unroll
        for (int mt = 0; mt < 4; mt++) {
#pragma unroll
            for (int h = 0; h < 2; h++) {
                float s = rsum[mt][h];
                s += __shfl_xor_sync(0xffffffffu, s, 1);
                s += __shfl_xor_sync(0xffffffffu, s, 2);
                rsum[mt][h] = s;
            }
        }
        float* ss = (float*)smem;
        const int nWj = wid & 3;
        if (tg == 0) {
#pragma unroll
            for (int mt = 0; mt < 4; mt++) {
                ss[nWj * 128 + mW + mt * 16 + g]     = rsum[mt][0];
                ss[nWj * 128 + mW + mt * 16 + 8 + g] = rsum[mt][1];
            }
        }
        __syncthreads();
        if (tid < 128) {
            float t = ss[tid] + ss[128 + tid] + ss[256 + tid] + ss[384 + tid];
            aux[((size_t)blockIdx.z * 16 + blockIdx.x) * Sn + m0 + tid] = t;
        }
    }
}

// ================= 3-MMA bf16 GEMM (v projection only) =======================
#define STAGE_BYTES 32768
#define SM_TOTAL    (NSTAGE * STAGE_BYTES)

__global__ void __launch_bounds__(256)
gemm_v(const bf16* __restrict__ Ah, const bf16* __restrict__ Al,
       const bf16* __restrict__ Bh, const bf16* __restrict__ Bl,
       const float* __restrict__ bias,
       __half* __restrict__ Ch, __half* __restrict__ Cl,
       int lda, int ldb, int ldc, int nK,
       size_t sA, size_t sB, size_t sC)
{
    extern __shared__ __align__(1024) char smem[];
    const uint32_t sm = smem_u32(smem);
    const int tid  = threadIdx.x;
    const int lane = tid & 31;
    const int wid  = tid >> 5;
    const int m0   = blockIdx.y * 128;
    const int n0   = blockIdx.x * 128;
    const int mW   = (wid >> 2) * 64;
    const int nW   = (wid & 3) * 32;

    Ah += (size_t)blockIdx.z * sA;  Al += (size_t)blockIdx.z * sA;
    Bh += (size_t)blockIdx.z * sB;  Bl += (size_t)blockIdx.z * sB;

    float acc[4][4][4];
#pragma unroll
    for (int i = 0; i < 4; i++)
#pragma unroll
        for (int j = 0; j < 4; j++) {
            acc[i][j][0] = 0.f; acc[i][j][1] = 0.f; acc[i][j][2] = 0.f; acc[i][j][3] = 0.f;
        }

    const uint32_t rl   = lane & 15;
    const uint32_t khA  = lane >> 4;
    const uint32_t swA  = (rl >> 1) & 3;
    const uint32_t aRow = (uint32_t)(mW + rl) * 64;
    const uint32_t rnl  = ((lane >> 4) << 3) | (lane & 7);
    const uint32_t khB  = (lane >> 3) & 1;
    const uint32_t swB  = (rnl >> 1) & 3;
    const uint32_t bRow = (uint32_t)(nW + rnl) * 64;

#pragma unroll
    for (int p = 0; p < 2; p++) {
        if (p < nK) {
            const uint32_t st = sm + p * STAGE_BYTES;
            cp_tile(st,         Ah, lda, m0, p, tid);
            cp_tile(st + 8192,  Al, lda, m0, p, tid);
            cp_tile(st + 16384, Bh, ldb, n0, p, tid);
            cp_tile(st + 24576, Bl, ldb, n0, p, tid);
        }
        CP_COMMIT();
    }

    for (int i = 0; i < nK; i++) {
        CP_WAIT(1);
        __syncthreads();

        const uint32_t stg = sm + (uint32_t)(i % NSTAGE) * STAGE_BYTES;
#pragma unroll
        for (int ks = 0; ks < 2; ks++) {
            const uint32_t aCh = (uint32_t)((ks * 2 + khA) ^ swA) << 4;
            const uint32_t bCh = (uint32_t)((ks * 2 + khB) ^ swB) << 4;
            uint32_t ah[4][4], al[4][4], bh[8], bl[8];
#pragma unroll
            for (int mt = 0; mt < 4; mt++) {
                LDSM_X4(ah[mt][0], ah[mt][1], ah[mt][2], ah[mt][3],
                        stg + aRow + mt * 1024 + aCh);
                LDSM_X4(al[mt][0], al[mt][1], al[mt][2], al[mt][3],
                        stg + 8192 + aRow + mt * 1024 + aCh);
            }
            LDSM_X4(bh[0], bh[1], bh[2], bh[3], stg + 16384 + bRow + bCh);
            LDSM_X4(bh[4], bh[5], bh[6], bh[7], stg + 16384 + bRow + 1024 + bCh);
            LDSM_X4(bl[0], bl[1], bl[2], bl[3], stg + 24576 + bRow + bCh);
            LDSM_X4(bl[4], bl[5], bl[6], bl[7], stg + 24576 + bRow + 1024 + bCh);

#pragma unroll
            for (int mt = 0; mt < 4; mt++)
#pragma unroll
                for (int nt = 0; nt < 4; nt++) {
                    mma16816(acc[mt][nt], ah[mt], &bh[nt * 2]);
                    mma16816(acc[mt][nt], ah[mt], &bl[nt * 2]);
                    mma16816(acc[mt][nt], al[mt], &bh[nt * 2]);
                }
        }

        const int nx = i + 2;
        if (nx < nK) {
            const uint32_t st = sm + (uint32_t)(nx % NSTAGE) * STAGE_BYTES;
            cp_tile(st,         Ah, lda, m0, nx, tid);
            cp_tile(st + 8192,  Al, lda, m0, nx, tid);
            cp_tile(st + 16384, Bh, ldb, n0, nx, tid);
            cp_tile(st + 24576, Bl, ldb, n0, nx, tid);
        }
        CP_COMMIT();
    }

    const int g  = lane >> 2;
    const int tg = lane & 3;
#pragma unroll
    for (int mt = 0; mt < 4; mt++) {
        const int m = m0 + mW + mt * 16 + g;
        const float bm0 = bias[m];
        const float bm8 = bias[m + 8];
#pragma unroll
        for (int nt = 0; nt < 4; nt++) {
            const int n = n0 + nW + nt * 8 + tg * 2;
            float d0 = acc[mt][nt][0] + bm0;
            float d1 = acc[mt][nt][1] + bm0;
            float d2 = acc[mt][nt][2] + bm8;
            float d3 = acc[mt][nt][3] + bm8;
            __half h0, l0, h1, l1, h2, l2, h3, l3;
            split_hl_f16(d0, h0, l0); split_hl_f16(d1, h1, l1);
            split_hl_f16(d2, h2, l2); split_hl_f16(d3, h3, l3);
            __half* CH = Ch + (size_t)blockIdx.z * sC;
            __half* CL = Cl + (size_t)blockIdx.z * sC;
            *(__half2*)(CH + (size_t)m * ldc + n)       = __halves2half2(h0, h1);
            *(__half2*)(CH + (size_t)(m + 8) * ldc + n) = __halves2half2(h2, h3);
            *(__half2*)(CL + (size_t)m * ldc + n)       = __halves2half2(l0, l1);
            *(__half2*)(CL + (size_t)(m + 8) * ldc + n) = __halves2half2(l2, l3);
        }
    }
}

// ================= fp16 PV GEMM: out = (v @ E^T) * inv[s] ====================
#define PV_STAGE 24576
#define PV_SMEM  (NSTAGE * PV_STAGE)

__global__ void __launch_bounds__(256)
gemm_pv(const __half* __restrict__ Ah, const __half* __restrict__ Al,
        const __half* __restrict__ B,
        const float* __restrict__ inv, float* __restrict__ C,
        int nK)
{
    extern __shared__ __align__(1024) char smem[];
    const uint32_t sm = smem_u32(smem);
    const int tid  = threadIdx.x;
    const int lane = tid & 31;
    const int wid  = tid >> 5;
    const int m0   = blockIdx.y * 128;
    const int n0   = blockIdx.x * 128;
    const int mW   = (wid >> 2) * 64;
    const int nW   = (wid & 3) * 32;

    Ah += (size_t)blockIdx.z * OD * Sn;
    Al += (size_t)blockIdx.z * OD * Sn;
    B  += (size_t)blockIdx.z * Sn * Sn;
    C  += (size_t)blockIdx.z * OD * Sn;

    float acc[4][4][4];
#pragma unroll
    for (int i = 0; i < 4; i++)
#pragma unroll
        for (int j = 0; j < 4; j++) {
            acc[i][j][0] = 0.f; acc[i][j][1] = 0.f; acc[i][j][2] = 0.f; acc[i][j][3] = 0.f;
        }

    const uint32_t rl   = lane & 15;
    const uint32_t khA  = lane >> 4;
    const uint32_t swA  = (rl >> 1) & 3;
    const uint32_t aRow = (uint32_t)(mW + rl) * 64;
    const uint32_t rnl  = ((lane >> 4) << 3) | (lane & 7);
    const uint32_t khB  = (lane >> 3) & 1;
    const uint32_t swB  = (rnl >> 1) & 3;
    const uint32_t bRow = (uint32_t)(nW + rnl) * 64;

#pragma unroll
    for (int p = 0; p < 2; p++) {
        if (p < nK) {
            const uint32_t st = sm + p * PV_STAGE;
            cp_tile(st,         Ah, Sn, m0, p, tid);
            cp_tile(st + 8192,  Al, Sn, m0, p, tid);
            cp_tile(st + 16384, B,  Sn, n0, p, tid);
        }
        CP_COMMIT();
    }

    for (int i = 0; i < nK; i++) {
        CP_WAIT(1);
        __syncthreads();

        const uint32_t stg = sm + (uint32_t)(i % NSTAGE) * PV_STAGE;
#pragma unroll
        for (int ks = 0; ks < 2; ks++) {
            const uint32_t aCh = (uint32_t)((ks * 2 + khA) ^ swA) << 4;
            const uint32_t bCh = (uint32_t)((ks * 2 + khB) ^ swB) << 4;
            uint32_t ah[4][4], al[4][4], bh[8];
#pragma unroll
            for (int mt = 0; mt < 4; mt++) {
                LDSM_X4(ah[mt][0], ah[mt][1], ah[mt][2], ah[mt][3],
                        stg + aRow + mt * 1024 + aCh);
                LDSM_X4(al[mt][0], al[mt][1], al[mt][2], al[mt][3],
                        stg + 8192 + aRow + mt * 1024 + aCh);
            }
            LDSM_X4(bh[0], bh[1], bh[2], bh[3], stg + 16384 + bRow + bCh);
            LDSM_X4(bh[4], bh[5], bh[6], bh[7], stg + 16384 + bRow + 1024 + bCh);

#pragma unroll
            for (int mt = 0; mt < 4; mt++)
#pragma unroll
                for (int nt = 0; nt < 4; nt++) {
                    mma16816h(acc[mt][nt], ah[mt], &bh[nt * 2]);
                    mma16816h(acc[mt][nt], al[mt], &bh[nt * 2]);
                }
        }

        const int nx = i + 2;
        if (nx < nK) {
            const uint32_t st = sm + (uint32_t)(nx % NSTAGE) * PV_STAGE;
            cp_tile(st,         Ah, Sn, m0, nx, tid);
            cp_tile(st + 8192,  Al, Sn, m0, nx, tid);
            cp_tile(st + 16384, B,  Sn, n0, nx, tid);
        }
        CP_COMMIT();
    }

    const int g  = lane >> 2;
    const int tg = lane & 3;
#pragma unroll
    for (int mt = 0; mt < 4; mt++) {
        const int m = m0 + mW + mt * 16 + g;
#pragma unroll
        for (int nt = 0; nt < 4; nt++) {
            const int n = n0 + nW + nt * 8 + tg * 2;
            float2 iv = *(const float2*)(inv + (size_t)blockIdx.z * Sn + n);
            float2 o0 = { acc[mt][nt][0] * iv.x, acc[mt][nt][1] * iv.y };
            float2 o1 = { acc[mt][nt][2] * iv.x, acc[mt][nt][3] * iv.y };
            *(float2*)(C + (size_t)m * Sn + n)       = o0;
            *(float2*)(C + (size_t)(m + 8) * Sn + n) = o1;
        }
    }
}

// ---------------- converters --------------------------------------------------
__global__ void __launch_bounds__(256)
xpose_pack(const float* __restrict__ x, bf16* __restrict__ xh, bf16* __restrict__ xl)
{
    __shared__ float t[32][33];
    const int tx = threadIdx.x, ty = threadIdx.y;
    const int s0 = blockIdx.x * 32, c0 = blockIdx.y * 32;
    const size_t bi = (size_t)blockIdx.z * Cin * Sn;
    const size_t bo = (size_t)blockIdx.z * Sn * Cin;
#pragma unroll
    for (int j = ty; j < 32; j += 8)
        t[j][tx] = x[bi + (size_t)(c0 + j) * Sn + s0 + tx];
    __syncthreads();
#pragma unroll
    for (int j = ty; j < 32; j += 8) {
        bf16 h, l;
        split_hl(t[tx][j], h, l);
        xh[bo + (size_t)(s0 + j) * Cin + c0 + tx] = h;
        xl[bo + (size_t)(s0 + j) * Cin + c0 + tx] = l;
    }
}

__global__ void __launch_bounds__(256)
pack_f32(const float* __restrict__ in, bf16* __restrict__ oh, bf16* __restrict__ ol, int n4)
{
    int i = blockIdx.x * 256 + threadIdx.x;
    if (i < n4) {
        float4 v = ((const float4*)in)[i];
        bf16 h0, l0, h1, l1, h2, l2, h3, l3;
        split_hl(v.x, h0, l0); split_hl(v.y, h1, l1);
        split_hl(v.z, h2, l2); split_hl(v.w, h3, l3);
        uint2 ho, lo;
        ho.x = (uint32_t)__bfloat16_as_ushort(h0) | ((uint32_t)__bfloat16_as_ushort(h1) << 16);
        ho.y = (uint32_t)__bfloat16_as_ushort(h2) | ((uint32_t)__bfloat16_as_ushort(h3) << 16);
        lo.x = (uint32_t)__bfloat16_as_ushort(l0) | ((uint32_t)__bfloat16_as_ushort(l1) << 16);
        lo.y = (uint32_t)__bfloat16_as_ushort(l2) | ((uint32_t)__bfloat16_as_ushort(l3) << 16);
        ((uint2*)oh)[i] = ho;
        ((uint2*)ol)[i] = lo;
    }
}

__global__ void __launch_bounds__(256)
reduce_inv(const float* __restrict__ psum, float* __restrict__ inv)
{
    int i = blockIdx.x * 256 + threadIdx.x;
    int b = i >> 11, s = i & 2047;
    const float* p = psum + (size_t)b * 16 * Sn + s;
    float t = 0.f;
#pragma unroll
    for (int j = 0; j < 16; j++) t += p[(size_t)j * Sn];
    inv[i] = 1.0f / t;
}

// -----------------------------------------------------------------------------
extern "C" void kernel_launch(void* const* d_in, const int* in_sizes, int n_in,
                              void* d_out, int out_size)
{
    (void)in_sizes; (void)n_in; (void)out_size;
    const float* x  = (const float*)d_in[0];
    const float* wq = (const float*)d_in[1];
    const float* bq = (const float*)d_in[2];
    const float* wk = (const float*)d_in[3];
    const float* bk = (const float*)d_in[4];
    const float* wv = (const float*)d_in[5];
    const float* bv = (const float*)d_in[6];
    float* out = (float*)d_out;

    bf16 *xh, *xl, *wqkh, *wqkl, *wvh, *wvl, *qh, *kh, *kl;
    __half *vh, *vl, *eP;
    float *bqk, *psum, *inv;
    cudaGetSymbolAddress((void**)&xh,   g_xT_h);  cudaGetSymbolAddress((void**)&xl,   g_xT_l);
    cudaGetSymbolAddress((void**)&wqkh, g_wqk_h); cudaGetSymbolAddress((void**)&wqkl, g_wqk_l);
    cudaGetSymbolAddress((void**)&wvh,  g_wv_h);  cudaGetSymbolAddress((void**)&wvl,  g_wv_l);
    cudaGetSymbolAddress((void**)&bqk,  g_bqk);
    cudaGetSymbolAddress((void**)&qh,   g_q_h);
    cudaGetSymbolAddress((void**)&kh,   g_k_h);   cudaGetSymbolAddress((void**)&kl,   g_k_l);
    cudaGetSymbolAddress((void**)&vh,   g_v_h);   cudaGetSymbolAddress((void**)&vl,   g_v_l);
    cudaGetSymbolAddress((void**)&eP,   g_e);
    cudaGetSymbolAddress((void**)&psum, g_psum);  cudaGetSymbolAddress((void**)&inv,  g_inv);

    cudaFuncSetAttribute(gemm2<1>, cudaFuncAttributeMaxDynamicSharedMemorySize, SMEM2);
    cudaFuncSetAttribute(gemm2<3>, cudaFuncAttributeMaxDynamicSharedMemorySize, SMEM2);
    cudaFuncSetAttribute(gemm_v,   cudaFuncAttributeMaxDynamicSharedMemorySize, SM_TOTAL);
    cudaFuncSetAttribute(gemm_pv,  cudaFuncAttributeMaxDynamicSharedMemorySize, PV_SMEM);

    // ---- conversions ----
    xpose_pack<<<dim3(Sn / 32, Cin / 32, Bn), dim3(32, 8)>>>(x, xh, xl);
    pack_f32<<<(KD * Cin / 4 + 255) / 256, 256>>>(wq, wqkh, wqkl, KD * Cin / 4);
    pack_f32<<<(KD * Cin / 4 + 255) / 256, 256>>>(wk, wqkh + (size_t)KD * Cin,
                                                  wqkl + (size_t)KD * Cin, KD * Cin / 4);
    pack_f32<<<(OD * Cin / 4 + 255) / 256, 256>>>(wv, wvh, wvl, OD * Cin / 4);
    cudaMemcpyAsync(bqk,      bq, KD * sizeof(float), cudaMemcpyDeviceToDevice, 0);
    cudaMemcpyAsync(bqk + KD, bk, KD * sizeof(float), cudaMemcpyDeviceToDevice, 0);

    const size_t sxT = (size_t)Sn * Cin;
    const size_t sq  = (size_t)Sn * KD;
    const size_t sv  = (size_t)OD * Sn;
    const size_t ssc = (size_t)Sn * Sn;

    // qk = xh @ (Wqk_h+Wqk_l)^T + bias -> q bf16-hi, k bf16 hi/lo   [m=s, n=ch, k=c]
    gemm2<1><<<dim3(QKN / 128, Sn / 128, Bn), 256, SMEM2>>>(
        xh, wqkh, wqkl, bqk, nullptr, qh, kh, kl,
        Cin, Cin, KD, Cin / 32, sxT, 0, sq, 1.0f);

    // v = (Wv_h+Wv_l) @ (xh+xl) + bv -> (B,OD,S) fp16 HL   [m=o, n=s, k=c]
    gemm_v<<<dim3(Sn / 128, OD / 128, Bn), 256, SM_TOTAL>>>(
        wvh, wvl, xh, xl, bv, vh, vl,
        Cin, Cin, Sn, Cin / 32, 0, sxT, sv);

    // E = exp(qh @ (kh+kl)^T / sqrt(KD)) -> fp16 plane + psum   [m=s, n=t, k=kd]
    gemm2<3><<<dim3(Sn / 128, Sn / 128, Bn), 256, SMEM2>>>(
        qh, kh, kl, nullptr, psum, eP, nullptr, nullptr,
        KD, KD, Sn, KD / 32, sq, sq, ssc, 0.04419417382415922f);

    // inv rowsums
    reduce_inv<<<Bn * Sn / 256, 256>>>(psum, inv);

    // out = (v @ E^T) * inv[s] -> (B,OD,S) fp32 into d_out
    gemm_pv<<<dim3(Sn / 128, OD / 128, Bn), 256, PV_SMEM>>>(
        vh, vl, eP, inv, out, Sn / 32);
}

// round 11
// speedup vs baseline: 2.2286x; 1.4032x over previous
#include <cuda_runtime.h>
#include <cuda_fp16.h>
#include <cstdint>
#include <math.h>

#define Bn  8
#define Cin 1024
#define Sn  2048
#define KD  512
#define OD  1024
#define QKN 1024   // merged q|k output width

// ---------------- scratch (all fp16 planes) ----------------------------------
__device__ __align__(128) __half g_x16 [(size_t)Bn * Sn * Cin];  // xT fp16 (B,S,C)
__device__ __align__(128) __half g_wqk_h[(size_t)QKN * Cin];
__device__ __align__(128) __half g_wqk_l[(size_t)QKN * Cin];
__device__ __align__(128) __half g_wv_h[(size_t)OD * Cin];
__device__ __align__(128) __half g_wv_l[(size_t)OD * Cin];
__device__ __align__(128) float  g_bqk[QKN];
__device__ __align__(128) __half g_qk [(size_t)Bn * Sn * QKN];   // q cols 0-511, k 512-1023
__device__ __align__(128) __half g_v  [(size_t)Bn * OD * Sn];    // v fp16 (B,OD,S)
__device__ __align__(128) __half g_e  [(size_t)Bn * Sn * Sn];    // exp(scores) fp16
__device__ __align__(128) float  g_psum[(size_t)Bn * 16 * Sn];
__device__ __align__(128) float  g_inv[(size_t)Bn * Sn];

// ---------------- helpers ----------------------------------------------------
__device__ __forceinline__ uint32_t smem_u32(const void* p) {
    uint32_t a;
    asm("{ .reg .u64 t; cvta.to.shared.u64 t, %1; cvt.u32.u64 %0, t; }" : "=r"(a) : "l"(p));
    return a;
}

__device__ __forceinline__ void split_hl_f16(float v, __half& h, __half& l) {
    h = __float2half(v);
    l = __float2half(v - __half2float(h));
}

#define LDSM_X4(r0, r1, r2, r3, addr) \
    asm volatile("ldmatrix.sync.aligned.m8n8.x4.shared.b16 {%0,%1,%2,%3}, [%4];" \
                 : "=r"(r0), "=r"(r1), "=r"(r2), "=r"(r3) : "r"(addr))

__device__ __forceinline__ void mma16816h(float* d, const uint32_t* a, const uint32_t* b) {
    asm volatile(
        "mma.sync.aligned.m16n8k16.row.col.f32.f16.f16.f32 "
        "{%0,%1,%2,%3}, {%4,%5,%6,%7}, {%8,%9}, {%0,%1,%2,%3};"
        : "+f"(d[0]), "+f"(d[1]), "+f"(d[2]), "+f"(d[3])
        : "r"(a[0]), "r"(a[1]), "r"(a[2]), "r"(a[3]), "r"(b[0]), "r"(b[1]));
}

#define CP_ASYNC16(dst, src) \
    asm volatile("cp.async.cg.shared.global [%0], [%1], 16;" :: "r"(dst), "l"(src) : "memory")
#define CP_COMMIT()  asm volatile("cp.async.commit_group;" ::: "memory")
#define CP_WAIT(n)   asm volatile("cp.async.wait_group %0;" :: "n"(n) : "memory")

// tile: 128 rows x 32 fp16 (64B rows); 16B-chunk swizzle c4 ^= (row>>1)&3
__device__ __forceinline__ void cp_tile(uint32_t sdst, const __half* __restrict__ g,
                                        int ld, int row0, int kc, int tid) {
#pragma unroll
    for (int it = 0; it < 2; it++) {
        int slot = tid + it * 256;
        int row  = slot >> 2;
        int c4   = slot & 3;
        uint32_t off = (uint32_t)row * 64 + (uint32_t)((c4 ^ ((row >> 1) & 3)) << 4);
        CP_ASYNC16(sdst + off, g + (size_t)(row0 + row) * ld + kc * 32 + c4 * 8);
    }
}

#define NSTAGE 3

// ================= fp16 GEMM, NA/NB planes per operand =======================
// D[m,n] = alpha * sum_k (sum A planes)[m,k]*(sum B planes)[n,k]
// MMAs per fragment-pair = NA*NB (min(NA,NB)==1 always here).
// EPI: 1 = +bias[n], fp16 out          (qk projection)
//      2 = +bias[m], fp16 out          (v projection)
//      3 = exp(d) -> fp16 out + renormalized psum (scores)
//      4 = d * aux[b*Sn + n], fp32 out (PV, deferred normalization)
template<int NA, int NB, int EPI>
__global__ void __launch_bounds__(256)
gemm_f16(const __half* __restrict__ Ah, const __half* __restrict__ Al,
         const __half* __restrict__ Bh, const __half* __restrict__ Bl,
         const float* __restrict__ bias, float* __restrict__ aux,
         void* __restrict__ C,
         int lda, int ldb, int ldc, int nK,
         size_t sA, size_t sB, size_t sC, float alpha)
{
    constexpr uint32_t STG_B = (uint32_t)(NA + NB) * 8192u;
    extern __shared__ __align__(1024) char smem[];
    const uint32_t sm = smem_u32(smem);
    const int tid  = threadIdx.x;
    const int lane = tid & 31;
    const int wid  = tid >> 5;
    const int m0   = blockIdx.y * 128;
    const int n0   = blockIdx.x * 128;
    const int mW   = (wid >> 2) * 64;
    const int nW   = (wid & 3) * 32;

    Ah += (size_t)blockIdx.z * sA;  if (NA == 2) Al += (size_t)blockIdx.z * sA;
    Bh += (size_t)blockIdx.z * sB;  if (NB == 2) Bl += (size_t)blockIdx.z * sB;

    float acc[4][4][4];
#pragma unroll
    for (int i = 0; i < 4; i++)
#pragma unroll
        for (int j = 0; j < 4; j++) {
            acc[i][j][0] = 0.f; acc[i][j][1] = 0.f; acc[i][j][2] = 0.f; acc[i][j][3] = 0.f;
        }

    const uint32_t rl   = lane & 15;
    const uint32_t khA  = lane >> 4;
    const uint32_t swA  = (rl >> 1) & 3;
    const uint32_t aRow = (uint32_t)(mW + rl) * 64;
    const uint32_t rnl  = ((lane >> 4) << 3) | (lane & 7);
    const uint32_t khB  = (lane >> 3) & 1;
    const uint32_t swB  = (rnl >> 1) & 3;
    const uint32_t bRow = (uint32_t)(nW + rnl) * 64;
    const uint32_t bOff = (uint32_t)NA * 8192u;

#pragma unroll
    for (int p = 0; p < 2; p++) {
        if (p < nK) {
            const uint32_t st = sm + p * STG_B;
            cp_tile(st, Ah, lda, m0, p, tid);
            if (NA == 2) cp_tile(st + 8192, Al, lda, m0, p, tid);
            cp_tile(st + bOff, Bh, ldb, n0, p, tid);
            if (NB == 2) cp_tile(st + bOff + 8192, Bl, ldb, n0, p, tid);
        }
        CP_COMMIT();
    }

    for (int i = 0; i < nK; i++) {
        CP_WAIT(1);
        __syncthreads();

        const uint32_t stg = sm + (uint32_t)(i % NSTAGE) * STG_B;
#pragma unroll
        for (int ks = 0; ks < 2; ks++) {
            const uint32_t aCh = (uint32_t)((ks * 2 + khA) ^ swA) << 4;
            const uint32_t bCh = (uint32_t)((ks * 2 + khB) ^ swB) << 4;
            uint32_t a[NA][4][4], b[NB][8];
#pragma unroll
            for (int pa = 0; pa < NA; pa++)
#pragma unroll
                for (int mt = 0; mt < 4; mt++) {
                    LDSM_X4(a[pa][mt][0], a[pa][mt][1], a[pa][mt][2], a[pa][mt][3],
                            stg + pa * 8192 + aRow + mt * 1024 + aCh);
                }
#pragma unroll
            for (int pb = 0; pb < NB; pb++) {
                LDSM_X4(b[pb][0], b[pb][1], b[pb][2], b[pb][3],
                        stg + bOff + pb * 8192 + bRow + bCh);
                LDSM_X4(b[pb][4], b[pb][5], b[pb][6], b[pb][7],
                        stg + bOff + pb * 8192 + bRow + 1024 + bCh);
            }

#pragma unroll
            for (int mt = 0; mt < 4; mt++)
#pragma unroll
                for (int nt = 0; nt < 4; nt++)
#pragma unroll
                    for (int pa = 0; pa < NA; pa++)
#pragma unroll
                        for (int pb = 0; pb < NB; pb++)
                            mma16816h(acc[mt][nt], a[pa][mt], &b[pb][nt * 2]);
        }

        const int nx = i + 2;
        if (nx < nK) {
            const uint32_t st = sm + (uint32_t)(nx % NSTAGE) * STG_B;
            cp_tile(st, Ah, lda, m0, nx, tid);
            if (NA == 2) cp_tile(st + 8192, Al, lda, m0, nx, tid);
            cp_tile(st + bOff, Bh, ldb, n0, nx, tid);
            if (NB == 2) cp_tile(st + bOff + 8192, Bl, ldb, n0, nx, tid);
        }
        CP_COMMIT();
    }
    __syncthreads();   // mainloop done; smem reusable below

    // ---- epilogue ----
    const int g  = lane >> 2;
    const int tg = lane & 3;
    float rsum[4][2];
    if (EPI == 3) {
#pragma unroll
        for (int mt = 0; mt < 4; mt++) { rsum[mt][0] = 0.f; rsum[mt][1] = 0.f; }
    }

#pragma unroll
    for (int mt = 0; mt < 4; mt++) {
        const int m = m0 + mW + mt * 16 + g;
        float bm0 = 0.f, bm8 = 0.f;
        if (EPI == 2) { bm0 = bias[m]; bm8 = bias[m + 8]; }
#pragma unroll
        for (int nt = 0; nt < 4; nt++) {
            const int n = n0 + nW + nt * 8 + tg * 2;
            float d0 = acc[mt][nt][0] * alpha;
            float d1 = acc[mt][nt][1] * alpha;
            float d2 = acc[mt][nt][2] * alpha;
            float d3 = acc[mt][nt][3] * alpha;
            if (EPI == 1) {
                float2 bb = *(const float2*)(bias + n);
                d0 += bb.x; d1 += bb.y; d2 += bb.x; d3 += bb.y;
            } else if (EPI == 2) {
                d0 += bm0; d1 += bm0; d2 += bm8; d3 += bm8;
            }
            if (EPI == 4) {
                float2 iv = *(const float2*)(aux + (size_t)blockIdx.z * Sn + n);
                float* Cf = (float*)C + (size_t)blockIdx.z * sC;
                float2 o0 = { d0 * iv.x, d1 * iv.y };
                float2 o1 = { d2 * iv.x, d3 * iv.y };
                *(float2*)(Cf + (size_t)m * ldc + n)       = o0;
                *(float2*)(Cf + (size_t)(m + 8) * ldc + n) = o1;
            } else {
                __half e0, e1, e2, e3;
                if (EPI == 3) {
                    e0 = __float2half(__expf(d0));
                    e1 = __float2half(__expf(d1));
                    e2 = __float2half(__expf(d2));
                    e3 = __float2half(__expf(d3));
                    // accumulate ROUNDED values -> normalization exact
                    rsum[mt][0] += __half2float(e0) + __half2float(e1);
                    rsum[mt][1] += __half2float(e2) + __half2float(e3);
                } else {
                    e0 = __float2half(d0); e1 = __float2half(d1);
                    e2 = __float2half(d2); e3 = __float2half(d3);
                }
                __half* Ch = (__half*)C + (size_t)blockIdx.z * sC;
                *(__half2*)(Ch + (size_t)m * ldc + n)       = __halves2half2(e0, e1);
                *(__half2*)(Ch + (size_t)(m + 8) * ldc + n) = __halves2half2(e2, e3);
            }
        }
    }

    if (EPI == 3) {
#pragma unroll
        for (int mt = 0; mt < 4; mt++) {
#pragma unroll
            for (int h = 0; h < 2; h++) {
                float s = rsum[mt][h];
                s += __shfl_xor_sync(0xffffffffu, s, 1);
                s += __shfl_xor_sync(0xffffffffu, s, 2);
                rsum[mt][h] = s;
            }
        }
        float* ss = (float*)smem;
        const int nWj = wid & 3;
        if (tg == 0) {
#pragma unroll
            for (int mt = 0; mt < 4; mt++) {
                ss[nWj * 128 + mW + mt * 16 + g]     = rsum[mt][0];
                ss[nWj * 128 + mW + mt * 16 + 8 + g] = rsum[mt][1];
            }
        }
        __syncthreads();
        if (tid < 128) {
            float t = ss[tid] + ss[128 + tid] + ss[256 + tid] + ss[384 + tid];
            aux[((size_t)blockIdx.z * 16 + blockIdx.x) * Sn + m0 + tid] = t;
        }
    }
}

// ---------------- converters --------------------------------------------------
// x (B,C,S) fp32 -> xT (B,S,C) fp16 single plane
__global__ void __launch_bounds__(256)
xpose16(const float* __restrict__ x, __half* __restrict__ xT)
{
    __shared__ float t[32][33];
    const int tx = threadIdx.x, ty = threadIdx.y;
    const int s0 = blockIdx.x * 32, c0 = blockIdx.y * 32;
    const size_t bi = (size_t)blockIdx.z * Cin * Sn;
    const size_t bo = (size_t)blockIdx.z * Sn * Cin;
#pragma unroll
    for (int j = ty; j < 32; j += 8)
        t[j][tx] = x[bi + (size_t)(c0 + j) * Sn + s0 + tx];
    __syncthreads();
#pragma unroll
    for (int j = ty; j < 32; j += 8)
        xT[bo + (size_t)(s0 + j) * Cin + c0 + tx] = __float2half(t[tx][j]);
}

// fp32 -> fp16 hi/lo planes
__global__ void __launch_bounds__(256)
pack_w16(const float* __restrict__ in, __half* __restrict__ oh, __half* __restrict__ ol, int n4)
{
    int i = blockIdx.x * 256 + threadIdx.x;
    if (i < n4) {
        float4 v = ((const float4*)in)[i];
        __half h0, l0, h1, l1, h2, l2, h3, l3;
        split_hl_f16(v.x, h0, l0); split_hl_f16(v.y, h1, l1);
        split_hl_f16(v.z, h2, l2); split_hl_f16(v.w, h3, l3);
        __half2 ho0 = __halves2half2(h0, h1), ho1 = __halves2half2(h2, h3);
        __half2 lo0 = __halves2half2(l0, l1), lo1 = __halves2half2(l2, l3);
        ((__half2*)oh)[i * 2]     = ho0;
        ((__half2*)oh)[i * 2 + 1] = ho1;
        ((__half2*)ol)[i * 2]     = lo0;
        ((__half2*)ol)[i * 2 + 1] = lo1;
    }
}

__global__ void __launch_bounds__(256)
reduce_inv(const float* __restrict__ psum, float* __restrict__ inv)
{
    int i = blockIdx.x * 256 + threadIdx.x;
    int b = i >> 11, s = i & 2047;
    const float* p = psum + (size_t)b * 16 * Sn + s;
    float t = 0.f;
#pragma unroll
    for (int j = 0; j < 16; j++) t += p[(size_t)j * Sn];
    inv[i] = 1.0f / t;
}

// -----------------------------------------------------------------------------
extern "C" void kernel_launch(void* const* d_in, const int* in_sizes, int n_in,
                              void* d_out, int out_size)
{
    (void)in_sizes; (void)n_in; (void)out_size;
    const float* x  = (const float*)d_in[0];
    const float* wq = (const float*)d_in[1];
    const float* bq = (const float*)d_in[2];
    const float* wk = (const float*)d_in[3];
    const float* bk = (const float*)d_in[4];
    const float* wv = (const float*)d_in[5];
    const float* bv = (const float*)d_in[6];
    float* out = (float*)d_out;

    __half *x16, *wqkh, *wqkl, *wvh, *wvl, *qk16, *v16, *eP;
    float *bqk, *psum, *inv;
    cudaGetSymbolAddress((void**)&x16,  g_x16);
    cudaGetSymbolAddress((void**)&wqkh, g_wqk_h); cudaGetSymbolAddress((void**)&wqkl, g_wqk_l);
    cudaGetSymbolAddress((void**)&wvh,  g_wv_h);  cudaGetSymbolAddress((void**)&wvl,  g_wv_l);
    cudaGetSymbolAddress((void**)&bqk,  g_bqk);
    cudaGetSymbolAddress((void**)&qk16, g_qk);
    cudaGetSymbolAddress((void**)&v16,  g_v);
    cudaGetSymbolAddress((void**)&eP,   g_e);
    cudaGetSymbolAddress((void**)&psum, g_psum);  cudaGetSymbolAddress((void**)&inv,  g_inv);

    const int SM12 = NSTAGE * 3 * 8192;   // 72 KB for 3-plane stages
    const int SM11 = NSTAGE * 2 * 8192;   // 48 KB for 2-plane stages
    cudaFuncSetAttribute(gemm_f16<1, 2, 1>, cudaFuncAttributeMaxDynamicSharedMemorySize, SM12);
    cudaFuncSetAttribute(gemm_f16<2, 1, 2>, cudaFuncAttributeMaxDynamicSharedMemorySize, SM12);
    cudaFuncSetAttribute(gemm_f16<1, 1, 3>, cudaFuncAttributeMaxDynamicSharedMemorySize, SM11);
    cudaFuncSetAttribute(gemm_f16<1, 1, 4>, cudaFuncAttributeMaxDynamicSharedMemorySize, SM11);

    // ---- conversions ----
    xpose16<<<dim3(Sn / 32, Cin / 32, Bn), dim3(32, 8)>>>(x, x16);
    pack_w16<<<(KD * Cin / 4 + 255) / 256, 256>>>(wq, wqkh, wqkl, KD * Cin / 4);
    pack_w16<<<(KD * Cin / 4 + 255) / 256, 256>>>(wk, wqkh + (size_t)KD * Cin,
                                                  wqkl + (size_t)KD * Cin, KD * Cin / 4);
    pack_w16<<<(OD * Cin / 4 + 255) / 256, 256>>>(wv, wvh, wvl, OD * Cin / 4);
    cudaMemcpyAsync(bqk,      bq, KD * sizeof(float), cudaMemcpyDeviceToDevice, 0);
    cudaMemcpyAsync(bqk + KD, bk, KD * sizeof(float), cudaMemcpyDeviceToDevice, 0);

    const size_t sxT = (size_t)Sn * Cin;
    const size_t sqk = (size_t)Sn * QKN;
    const size_t sv  = (size_t)OD * Sn;
    const size_t ssc = (size_t)Sn * Sn;

    // qk = x16 @ (Wqk_h+Wqk_l)^T + bias -> (B,S,1024) fp16   [m=s, n=ch, k=c]
    gemm_f16<1, 2, 1><<<dim3(QKN / 128, Sn / 128, Bn), 256, SM12>>>(
        x16, nullptr, wqkh, wqkl, bqk, nullptr, qk16,
        Cin, Cin, QKN, Cin / 32, sxT, 0, sqk, 1.0f);

    // v = (Wv_h+Wv_l) @ x16 + bv -> (B,OD,S) fp16   [m=o, n=s, k=c]
    gemm_f16<2, 1, 2><<<dim3(Sn / 128, OD / 128, Bn), 256, SM12>>>(
        wvh, wvl, x16, nullptr, bv, nullptr, v16,
        Cin, Cin, Sn, Cin / 32, 0, sxT, sv, 1.0f);

    // E = exp(q16 @ k16^T / sqrt(KD)) -> fp16 + psum   [m=s, n=t, k=kd]
    gemm_f16<1, 1, 3><<<dim3(Sn / 128, Sn / 128, Bn), 256, SM11>>>(
        qk16, nullptr, qk16 + KD, nullptr, nullptr, psum, eP,
        QKN, QKN, Sn, KD / 32, sqk, sqk, ssc, 0.04419417382415922f);

    // inv rowsums
    reduce_inv<<<Bn * Sn / 256, 256>>>(psum, inv);

    // out = (v16 @ E^T) * inv[s] -> (B,OD,S) fp32 into d_out   [m=o, n=s, k=t]
    gemm_f16<1, 1, 4><<<dim3(Sn / 128, OD / 128, Bn), 256, SM11>>>(
        v16, nullptr, eP, nullptr, nullptr, inv, out,
        Sn, Sn, Sn, Sn / 32, sv, ssc, sv, 1.0f);
}